// round 3
// baseline (speedup 1.0000x reference)
#include <cuda_runtime.h>
#include <math.h>
#include <stdint.h>

#define HH   256
#define WW   256
#define HW   65536
#define WHF  129            // rfft width
#define DIM  128
#define HID  512
#define NB   4
#define NLAYERS 4

// ---------------- scratch (device globals: allocation-free) ----------------
__device__ float  g_h[NB * DIM * HW];                 // 134 MB
__device__ float  g_y[NB * HID * HW];                 // 537 MB
__device__ float  g_z[NB * DIM * HW];                 // 134 MB
__device__ float2 g_xf[(size_t)NB * DIM * WHF * 256]; // 135 MB  [(b*128+c)*129+kx][y]
__device__ float2 g_filt[(size_t)DIM * WHF * 256];    // 34 MB   [c][kx][brev8(ky)]

// ---------------- helpers ----------------
__device__ __forceinline__ int brev8(int x) { return (int)(__brev((unsigned)x) >> 24); }
__device__ __forceinline__ float2 cadd(float2 a, float2 b){ return make_float2(a.x+b.x, a.y+b.y); }
__device__ __forceinline__ float2 csub(float2 a, float2 b){ return make_float2(a.x-b.x, a.y-b.y); }
__device__ __forceinline__ float2 cmul(float2 a, float2 b){
    return make_float2(a.x*b.x - a.y*b.y, a.x*b.y + a.y*b.x);
}

// twiddle init: tw[k] = exp(-2*pi*i*k/256), k in [0,128)
#define TW_INIT()                                                        \
    do { if (threadIdx.x < 128) {                                        \
        float s_, c_;                                                    \
        sincospif(-(float)threadIdx.x / 128.0f, &s_, &c_);               \
        tw[threadIdx.x] = make_float2(c_, s_);                           \
    } } while (0)

// DIF forward: natural input -> bit-reversed output. 16 rows x 256 pts in smem.
#define FFT_DIF(dmat)                                                    \
    for (int s_ = 0; s_ < 8; s_++) {                                     \
        __syncthreads();                                                 \
        int half_ = 128 >> s_;                                           \
        for (int q_ = threadIdx.x; q_ < 2048; q_ += 256) {               \
            int r_ = q_ >> 7, j_ = q_ & 127;                             \
            int p_ = j_ & (half_ - 1);                                   \
            int i0_ = ((j_ >> (7 - s_)) << (8 - s_)) + p_;               \
            float2 u_ = dmat[r_][i0_];                                   \
            float2 v_ = dmat[r_][i0_ + half_];                           \
            float2 w_ = tw[p_ << s_];                                    \
            dmat[r_][i0_]          = cadd(u_, v_);                       \
            dmat[r_][i0_ + half_]  = cmul(csub(u_, v_), w_);             \
        }                                                                \
    }                                                                    \
    __syncthreads();

// DIT inverse (conj twiddles, unscaled): bit-reversed input -> natural output.
#define FFT_DIT_INV(dmat)                                                \
    for (int s_ = 0; s_ < 8; s_++) {                                     \
        __syncthreads();                                                 \
        int half_ = 1 << s_;                                             \
        for (int q_ = threadIdx.x; q_ < 2048; q_ += 256) {               \
            int r_ = q_ >> 7, j_ = q_ & 127;                             \
            int p_ = j_ & (half_ - 1);                                   \
            int i0_ = ((j_ >> s_) << (s_ + 1)) + p_;                     \
            float2 w_ = tw[p_ << (7 - s_)];                              \
            w_.y = -w_.y;                                                \
            float2 t_ = cmul(dmat[r_][i0_ + half_], w_);                 \
            float2 u_ = dmat[r_][i0_];                                   \
            dmat[r_][i0_]         = cadd(u_, t_);                        \
            dmat[r_][i0_ + half_] = csub(u_, t_);                        \
        }                                                                \
    }                                                                    \
    __syncthreads();

// ---------------- encoder: h = (enc_w @ x + enc_b)*8 + pos ----------------
__global__ void enc_kernel(const float* __restrict__ x, const float* __restrict__ w,
                           const float* __restrict__ bias, const float* __restrict__ pos,
                           float* __restrict__ h)
{
    int idx = blockIdx.x * 256 + threadIdx.x;
    if (idx >= NB * DIM * HW) return;
    int p = idx & (HW - 1);
    int o = (idx >> 16) & (DIM - 1);
    int b = idx >> 23;
    float x0 = x[(size_t)(b * 2 + 0) * HW + p];
    float x1 = x[(size_t)(b * 2 + 1) * HW + p];
    float v = (w[o * 2] * x0 + w[o * 2 + 1] * x1 + bias[o]) * 8.0f
              + pos[(size_t)o * HW + p];
    h[idx] = v;
}

// ---------------- decoder: out = (dec_w @ h + dec_b)/8 ----------------
__global__ void dec_kernel(const float* __restrict__ h, const float* __restrict__ w,
                           const float* __restrict__ bias, float* __restrict__ out)
{
    int idx = blockIdx.x * 256 + threadIdx.x;
    if (idx >= NB * HW) return;
    int p = idx & (HW - 1);
    int b = idx >> 16;
    const float* hb = h + (size_t)b * DIM * HW + p;
    float a0 = 0.f, a1 = 0.f;
#pragma unroll 4
    for (int c = 0; c < DIM; c++) {
        float hv = hb[(size_t)c * HW];
        a0 += w[c] * hv;
        a1 += w[DIM + c] * hv;
    }
    out[(size_t)(b * 2 + 0) * HW + p] = (a0 + bias[0]) * 0.125f;
    out[(size_t)(b * 2 + 1) * HW + p] = (a1 + bias[1]) * 0.125f;
}

// ---------------- per-layer filter precompute (bit-reversed ky order) ----------------
// filt = mask ? sigmoid(mag)*exp(i*phase)/65536 : 0
__global__ void prep_filt(const float* __restrict__ mags, const float* __restrict__ phases,
                          float2* __restrict__ filt)
{
    int idx = blockIdx.x * 256 + threadIdx.x;
    if (idx >= DIM * HH * WHF) return;
    int kx = idx % WHF;
    int ky = (idx / WHF) % HH;
    int c  = idx / (WHF * HH);
    int kyp = (ky <= 128) ? ky : (256 - ky);
    float2 o = make_float2(0.f, 0.f);
    if (kx * kx + kyp * kyp <= 16384) {
        float m  = mags[idx];
        float ph = phases[idx];
        float sig = 1.0f / (1.0f + __expf(-m));
        float s, co;
        sincosf(ph, &s, &co);
        float sc = sig * (1.0f / 65536.0f);
        o = make_float2(sc * co, sc * s);
    }
    filt[(size_t)c * (WHF * 256) + (size_t)kx * 256 + brev8(ky)] = o;
}

// ---------------- FFT A: forward real row FFT (along W), write transposed half-spectrum ----------------
__global__ void fft_row_fwd(const float* __restrict__ z, float2* __restrict__ xf)
{
    __shared__ float2 d[16][256];
    __shared__ float2 tw[128];
    TW_INIT();
    int img = blockIdx.x;
    int y0  = blockIdx.y * 16;
    const float* src = z + (size_t)img * HW + (size_t)y0 * 256;
    for (int idx = threadIdx.x; idx < 4096; idx += 256)
        d[idx >> 8][idx & 255] = make_float2(src[idx], 0.f);
    FFT_DIF(d);
    float2* dst = xf + (size_t)img * (WHF * 256) + y0;
    for (int idx = threadIdx.x; idx < WHF * 16; idx += 256) {
        int kx = idx >> 4, ry = idx & 15;
        dst[(size_t)kx * 256 + ry] = d[ry][brev8(kx)];   // spectrum kx lives at brev(kx)
    }
}

// ---------------- FFT B: fused column fwd FFT -> complex filter -> column inv FFT ----------------
__global__ void fft_col(float2* __restrict__ xf, const float2* __restrict__ filt)
{
    __shared__ float2 d[16][256];
    __shared__ float2 tw[128];
    TW_INIT();
    size_t l0 = (size_t)blockIdx.x * 16;
    float2* src = xf + l0 * 256;
    float2* df = &d[0][0];
    for (int idx = threadIdx.x; idx < 4096; idx += 256)
        df[idx] = src[idx];
    FFT_DIF(d);
    for (int idx = threadIdx.x; idx < 4096; idx += 256) {
        int r = idx >> 8;
        size_t fl = ((l0 + r) % (size_t)(DIM * WHF)) * 256;  // (c,kx) filter line
        float2 f = filt[fl + (idx & 255)];                    // stored bit-reversed in ky
        df[idx] = cmul(df[idx], f);
    }
    FFT_DIT_INV(d);
    for (int idx = threadIdx.x; idx < 4096; idx += 256)
        src[idx] = df[idx];
}

// ---------------- FFT C: inverse row FFT (c2r along W) ----------------
__global__ void fft_row_inv(const float2* __restrict__ xf, float* __restrict__ z)
{
    __shared__ float2 d[16][256];
    __shared__ float2 tw[128];
    TW_INIT();
    int img = blockIdx.x;
    int y0  = blockIdx.y * 16;
    const float2* src = xf + (size_t)img * (WHF * 256) + y0;
    for (int idx = threadIdx.x; idx < WHF * 16; idx += 256) {
        int kx = idx >> 4, ry = idx & 15;
        d[ry][brev8(kx)] = src[(size_t)kx * 256 + ry];
    }
    __syncthreads();
    // Hermitian fill: X[k] = conj(X[256-k]) for k=129..255, placed at brev(k)
    for (int q = threadIdx.x; q < 16 * 127; q += 256) {
        int r = q / 127;
        int k = 129 + (q % 127);
        float2 v = d[r][brev8(256 - k)];
        d[r][brev8(k)] = make_float2(v.x, -v.y);
    }
    FFT_DIT_INV(d);
    float* dst = z + (size_t)img * HW + (size_t)y0 * 256;
    for (int idx = threadIdx.x; idx < 4096; idx += 256)
        dst[idx] = d[idx >> 8][idx & 255].x;   // real part
}

// ---------------- SGEMM: C(MxN) = A(MxK) @ B(KxN), row-major, batch in grid.z ----------------
// EPI: 0 = +bias, 1 = silu(+bias), 2 = +bias + residual add into C
template <int EPI>
__global__ void __launch_bounds__(256)
sgemm(const float* __restrict__ A, const float* __restrict__ Bm,
      const float* __restrict__ bias, float* __restrict__ Cm,
      int M, int N, int K)
{
    const float* Bp = Bm + (size_t)blockIdx.z * (size_t)K * N;
    float*       Cp = Cm + (size_t)blockIdx.z * (size_t)M * N;

    __shared__ float As[8][128];
    __shared__ float Bs[8][128];

    int tid  = threadIdx.x;
    int trow = tid >> 4;          // 0..15
    int tcol = tid & 15;          // 0..15

    const float* Ab = A + (size_t)blockIdx.y * 128 * K;
    const float* Bb = Bp + (size_t)blockIdx.x * 128;

    int aRow = tid >> 1;          // 0..127
    int aCol = (tid & 1) * 4;     // 0 or 4
    int bRow = tid >> 5;          // 0..7
    int bCol = (tid & 31) * 4;    // 0..124

    float acc[8][8];
#pragma unroll
    for (int i = 0; i < 8; i++)
#pragma unroll
        for (int j = 0; j < 8; j++) acc[i][j] = 0.f;

    for (int k0 = 0; k0 < K; k0 += 8) {
        float4 av = *(const float4*)(Ab + (size_t)aRow * K + k0 + aCol);
        As[aCol + 0][aRow] = av.x;
        As[aCol + 1][aRow] = av.y;
        As[aCol + 2][aRow] = av.z;
        As[aCol + 3][aRow] = av.w;
        float4 bv = *(const float4*)(Bb + (size_t)(k0 + bRow) * N + bCol);
        *(float4*)&Bs[bRow][bCol] = bv;
        __syncthreads();
#pragma unroll
        for (int kk = 0; kk < 8; kk++) {
            float4 a0 = *(float4*)&As[kk][trow * 8];
            float4 a1 = *(float4*)&As[kk][trow * 8 + 4];
            float4 b0 = *(float4*)&Bs[kk][tcol * 8];
            float4 b1 = *(float4*)&Bs[kk][tcol * 8 + 4];
            float ra[8] = {a0.x, a0.y, a0.z, a0.w, a1.x, a1.y, a1.z, a1.w};
            float rb[8] = {b0.x, b0.y, b0.z, b0.w, b1.x, b1.y, b1.z, b1.w};
#pragma unroll
            for (int i = 0; i < 8; i++)
#pragma unroll
                for (int j = 0; j < 8; j++)
                    acc[i][j] += ra[i] * rb[j];
        }
        __syncthreads();
    }

#pragma unroll
    for (int i = 0; i < 8; i++) {
        int row = blockIdx.y * 128 + trow * 8 + i;
        float bi = bias[row];
        float* crow = Cp + (size_t)row * N + (size_t)blockIdx.x * 128 + tcol * 8;
#pragma unroll
        for (int j = 0; j < 8; j += 4) {
            float4 v;
            v.x = acc[i][j + 0] + bi;
            v.y = acc[i][j + 1] + bi;
            v.z = acc[i][j + 2] + bi;
            v.w = acc[i][j + 3] + bi;
            if (EPI == 1) {
                v.x = v.x / (1.f + __expf(-v.x));
                v.y = v.y / (1.f + __expf(-v.y));
                v.z = v.z / (1.f + __expf(-v.z));
                v.w = v.w / (1.f + __expf(-v.w));
            }
            if (EPI == 2) {
                float4 old = *(float4*)(crow + j);
                v.x += old.x; v.y += old.y; v.z += old.z; v.w += old.w;
            }
            *(float4*)(crow + j) = v;
        }
    }
}

// ---------------- launch ----------------
extern "C" void kernel_launch(void* const* d_in, const int* in_sizes, int n_in,
                              void* d_out, int out_size)
{
    const float* x      = (const float*)d_in[0];
    const float* enc_w  = (const float*)d_in[1];
    const float* enc_b  = (const float*)d_in[2];
    const float* pos    = (const float*)d_in[3];
    const float* w1     = (const float*)d_in[4];
    const float* b1     = (const float*)d_in[5];
    const float* w2     = (const float*)d_in[6];
    const float* b2     = (const float*)d_in[7];
    const float* mags   = (const float*)d_in[8];
    const float* phases = (const float*)d_in[9];
    const float* oxw    = (const float*)d_in[10];
    const float* oxb    = (const float*)d_in[11];
    const float* dw     = (const float*)d_in[12];
    const float* db     = (const float*)d_in[13];
    float* out = (float*)d_out;

    float  *h, *y, *z;
    float2 *xf, *ft;
    cudaGetSymbolAddress((void**)&h,  g_h);
    cudaGetSymbolAddress((void**)&y,  g_y);
    cudaGetSymbolAddress((void**)&z,  g_z);
    cudaGetSymbolAddress((void**)&xf, g_xf);
    cudaGetSymbolAddress((void**)&ft, g_filt);

    enc_kernel<<<(NB * DIM * HW + 255) / 256, 256>>>(x, enc_w, enc_b, pos, h);

    const size_t specL = (size_t)DIM * HH * WHF;
    for (int i = 0; i < NLAYERS; i++) {
        prep_filt<<<(int)((specL + 255) / 256), 256>>>(mags + i * specL, phases + i * specL, ft);

        dim3 g1(HW / 128, HID / 128, NB);
        sgemm<1><<<g1, 256>>>(w1 + (size_t)i * HID * DIM, h, b1 + i * HID, y, HID, HW, DIM);

        dim3 g2(HW / 128, DIM / 128, NB);
        sgemm<0><<<g2, 256>>>(w2 + (size_t)i * DIM * HID, y, b2 + i * DIM, z, DIM, HW, HID);

        fft_row_fwd<<<dim3(NB * DIM, 16), 256>>>(z, xf);
        fft_col<<<(NB * DIM * WHF) / 16, 256>>>(xf, ft);
        fft_row_inv<<<dim3(NB * DIM, 16), 256>>>(xf, z);

        sgemm<2><<<g2, 256>>>(oxw + (size_t)i * DIM * DIM, z, oxb + i * DIM, h, DIM, HW, DIM);
    }

    dec_kernel<<<(NB * HW + 255) / 256, 256>>>(h, dw, db, out);
}

// round 5
// speedup vs baseline: 1.1954x; 1.1954x over previous
#include <cuda_runtime.h>
#include <cuda_bf16.h>
#include <math.h>
#include <stdint.h>

#define HH   256
#define WW   256
#define HW   65536
#define WHF  129            // rfft width
#define DIM  128
#define HID  512
#define NB   4
#define NLAYERS 4

// ---------------- scratch (device globals: allocation-free) ----------------
__device__ float  g_h[NB * DIM * HW];                 // 134 MB  [b][c][p]
__device__ float  g_y[NB * HID * HW];                 // 537 MB
__device__ float  g_z[NB * DIM * HW];                 // 134 MB
__device__ float2 g_xf[(size_t)NB * DIM * WHF * 256]; // 135 MB  [(b*128+c)*129+kx][y]
__device__ float2 g_filt[(size_t)DIM * WHF * 256];    // 34 MB   [c][kx][brev8(ky)]

// ---------------- helpers ----------------
__device__ __forceinline__ int brev8(int x) { return (int)(__brev((unsigned)x) >> 24); }
__device__ __forceinline__ float2 cadd(float2 a, float2 b){ return make_float2(a.x+b.x, a.y+b.y); }
__device__ __forceinline__ float2 csub(float2 a, float2 b){ return make_float2(a.x-b.x, a.y-b.y); }
__device__ __forceinline__ float2 cmul(float2 a, float2 b){
    return make_float2(a.x*b.x - a.y*b.y, a.x*b.y + a.y*b.x);
}
__device__ __forceinline__ uint32_t smem_u32(const void* p) {
    uint32_t a;
    asm("{ .reg .u64 t; cvta.to.shared.u64 t, %1; cvt.u32.u64 %0, t; }" : "=r"(a) : "l"(p));
    return a;
}

// ================= mma.sync helpers (legal on plain sm_103 PTX target) =================
__device__ __forceinline__ void ldsm4(uint32_t* r, uint32_t addr) {
    asm volatile("ldmatrix.sync.aligned.m8n8.x4.shared.b16 {%0,%1,%2,%3}, [%4];"
                 : "=r"(r[0]), "=r"(r[1]), "=r"(r[2]), "=r"(r[3]) : "r"(addr));
}
__device__ __forceinline__ void ldsm4t(uint32_t* r, uint32_t addr) {
    asm volatile("ldmatrix.sync.aligned.m8n8.x4.trans.shared.b16 {%0,%1,%2,%3}, [%4];"
                 : "=r"(r[0]), "=r"(r[1]), "=r"(r[2]), "=r"(r[3]) : "r"(addr));
}
__device__ __forceinline__ void mma16816(float* c, const uint32_t* a, const uint32_t* b) {
    asm volatile(
        "mma.sync.aligned.m16n8k16.row.col.f32.bf16.bf16.f32 "
        "{%0,%1,%2,%3}, {%4,%5,%6,%7}, {%8,%9}, {%0,%1,%2,%3};"
        : "+f"(c[0]), "+f"(c[1]), "+f"(c[2]), "+f"(c[3])
        : "r"(a[0]), "r"(a[1]), "r"(a[2]), "r"(a[3]), "r"(b[0]), "r"(b[1]));
}

// split fp32x4 -> hi/lo bf16x4, 8B each, at byte offset off in both buffers
__device__ __forceinline__ void split8(uint32_t hi_addr, uint32_t lo_addr, float4 v) {
    __nv_bfloat16 h0 = __float2bfloat16(v.x), h1 = __float2bfloat16(v.y);
    __nv_bfloat16 h2 = __float2bfloat16(v.z), h3 = __float2bfloat16(v.w);
    __nv_bfloat16 l0 = __float2bfloat16(v.x - __bfloat162float(h0));
    __nv_bfloat16 l1 = __float2bfloat16(v.y - __bfloat162float(h1));
    __nv_bfloat16 l2 = __float2bfloat16(v.z - __bfloat162float(h2));
    __nv_bfloat16 l3 = __float2bfloat16(v.w - __bfloat162float(h3));
    uint32_t ha = ((uint32_t)__bfloat16_as_ushort(h1) << 16) | __bfloat16_as_ushort(h0);
    uint32_t hb = ((uint32_t)__bfloat16_as_ushort(h3) << 16) | __bfloat16_as_ushort(h2);
    uint32_t la = ((uint32_t)__bfloat16_as_ushort(l1) << 16) | __bfloat16_as_ushort(l0);
    uint32_t lb = ((uint32_t)__bfloat16_as_ushort(l3) << 16) | __bfloat16_as_ushort(l2);
    asm volatile("st.shared.v2.b32 [%0], {%1, %2};" :: "r"(hi_addr), "r"(ha), "r"(hb) : "memory");
    asm volatile("st.shared.v2.b32 [%0], {%1, %2};" :: "r"(lo_addr), "r"(la), "r"(lb) : "memory");
}

// ================= tensor-core GEMM (3x bf16 split) =================
// C[m][n] = sum_k A[m][k]*B[k][n] + bias[m]  (+ epilogue), batch z
// A: weights [M][K] row-major (shared across batch); B: activations [K][HW]; C: [M][HW]
// EPI: 0 = bias, 1 = bias+silu, 2 = bias+residual (C += result)
template <int K, int EPI>
__global__ void __launch_bounds__(256, 1)
gemm_mma(const float* __restrict__ A, const float* __restrict__ B,
         const float* __restrict__ bias, float* __restrict__ C, int M)
{
    constexpr int NC = K / 32;
    __shared__ uint8_t smem[32768];   // [Ah 8K][Al 8K][Bh 8K][Bl 8K]
    uint32_t sb  = smem_u32(smem);
    uint32_t sAh = sb, sBh = sb + 16384;

    int tid  = threadIdx.x;
    int lane = tid & 31;
    int warp = tid >> 5;
    int wm = warp >> 1, wn = warp & 1;          // 4x2 warp grid (M x N)

    const float* Ab = A + (size_t)blockIdx.y * 128 * K;
    const float* Bb = B + (size_t)blockIdx.z * K * HW + blockIdx.x * 128;
    float*       Cp = C + (size_t)blockIdx.z * M * HW;

    // per-thread load slots (4 float4 each for A and B)
    int arow[4], ac4[4], bk[4], bc4[4];
#pragma unroll
    for (int t = 0; t < 4; t++) {
        int idx = tid + t * 256;
        arow[t] = ((idx >> 6) << 3) | (idx & 7);   // 0..127
        ac4[t]  = (idx >> 3) & 7;                  // 0..7 (k float4)
        bk[t]   = ((idx >> 8) << 3) | (idx & 7);   // 0..31
        bc4[t]  = (idx >> 3) & 31;                 // 0..31 (n float4)
    }

    float acc[2][8][4] = {};
    float4 pa[4], pb[4];
#pragma unroll
    for (int t = 0; t < 4; t++) {
        pa[t] = *(const float4*)(Ab + (size_t)arow[t] * K + ac4[t] * 4);
        pb[t] = *(const float4*)(Bb + (size_t)bk[t] * HW + bc4[t] * 4);
    }

    for (int c = 0; c < NC; c++) {
        // store current chunk into permuted tile layout
#pragma unroll
        for (int t = 0; t < 4; t++) {
            {   // A: tile (kb*8 + mb), chunk = (m&15) + kh*16
                int kb = ac4[t] >> 2, kh = (ac4[t] >> 1) & 1, kl = (ac4[t] & 1) * 4;
                int off = (kb * 8 + (arow[t] >> 4)) * 512 + ((arow[t] & 15) + kh * 16) * 16 + kl * 2;
                split8(sAh + off, sAh + 8192 + off, pa[t]);
            }
            {   // B: tile (kb*8 + nb), chunk = (k&15) + nh*16
                int nb = bc4[t] >> 2, nh = (bc4[t] >> 1) & 1, nl = (bc4[t] & 1) * 4;
                int off = ((bk[t] >> 4) * 8 + nb) * 512 + ((bk[t] & 15) + nh * 16) * 16 + nl * 2;
                split8(sBh + off, sBh + 8192 + off, pb[t]);
            }
        }
        __syncthreads();

        if (c + 1 < NC) {                        // prefetch next chunk
            int k0 = (c + 1) * 32;
#pragma unroll
            for (int t = 0; t < 4; t++) {
                pa[t] = *(const float4*)(Ab + (size_t)arow[t] * K + k0 + ac4[t] * 4);
                pb[t] = *(const float4*)(Bb + (size_t)(k0 + bk[t]) * HW + bc4[t] * 4);
            }
        }

#pragma unroll
        for (int kb = 0; kb < 2; kb++) {
            uint32_t ah[2][4], al[2][4], bh[4][4], bl[4][4];
#pragma unroll
            for (int i = 0; i < 2; i++) {
                uint32_t ad = sAh + (kb * 8 + wm * 2 + i) * 512 + lane * 16;
                ldsm4(ah[i], ad);
                ldsm4(al[i], ad + 8192);
            }
#pragma unroll
            for (int r = 0; r < 4; r++) {
                uint32_t bd = sBh + (kb * 8 + wn * 4 + r) * 512 + lane * 16;
                ldsm4t(bh[r], bd);
                ldsm4t(bl[r], bd + 8192);
            }
#pragma unroll
            for (int i = 0; i < 2; i++)
#pragma unroll
                for (int j = 0; j < 8; j++) {
                    const uint32_t* bhp = &bh[j >> 1][(j & 1) * 2];
                    const uint32_t* blp = &bl[j >> 1][(j & 1) * 2];
                    mma16816(acc[i][j], ah[i], bhp);
                    mma16816(acc[i][j], ah[i], blp);
                    mma16816(acc[i][j], al[i], bhp);
                }
        }
        __syncthreads();
    }

    // epilogue
    int g = lane >> 2;
    int mb0   = blockIdx.y * 128 + wm * 32;
    int nbase = blockIdx.x * 128 + wn * 64 + (lane & 3) * 2;
#pragma unroll
    for (int i = 0; i < 2; i++) {
        int r0 = mb0 + i * 16 + g;
        float bi0 = bias[r0], bi1 = bias[r0 + 8];
        float* row0 = Cp + (size_t)r0 * HW + nbase;
        float* row1 = row0 + (size_t)8 * HW;
#pragma unroll
        for (int j = 0; j < 8; j++) {
            float v0 = acc[i][j][0] + bi0, v1 = acc[i][j][1] + bi0;
            float v2 = acc[i][j][2] + bi1, v3 = acc[i][j][3] + bi1;
            if (EPI == 1) {
                v0 = v0 / (1.f + __expf(-v0)); v1 = v1 / (1.f + __expf(-v1));
                v2 = v2 / (1.f + __expf(-v2)); v3 = v3 / (1.f + __expf(-v3));
            }
            if (EPI == 2) {
                float2 o0 = *(float2*)(row0 + j * 8);
                float2 o1 = *(float2*)(row1 + j * 8);
                v0 += o0.x; v1 += o0.y; v2 += o1.x; v3 += o1.y;
            }
            *(float2*)(row0 + j * 8) = make_float2(v0, v1);
            *(float2*)(row1 + j * 8) = make_float2(v2, v3);
        }
    }
}

// ---------------- twiddles + FFT building blocks (verified in R3) ----------------
#define TW_INIT()                                                        \
    do { if (threadIdx.x < 128) {                                        \
        float s_, c_;                                                    \
        sincospif(-(float)threadIdx.x / 128.0f, &s_, &c_);               \
        tw[threadIdx.x] = make_float2(c_, s_);                           \
    } } while (0)

#define FFT_DIF(dmat)                                                    \
    for (int s_ = 0; s_ < 8; s_++) {                                     \
        __syncthreads();                                                 \
        int half_ = 128 >> s_;                                           \
        for (int q_ = threadIdx.x; q_ < 2048; q_ += 256) {               \
            int r_ = q_ >> 7, j_ = q_ & 127;                             \
            int p_ = j_ & (half_ - 1);                                   \
            int i0_ = ((j_ >> (7 - s_)) << (8 - s_)) + p_;               \
            float2 u_ = dmat[r_][i0_];                                   \
            float2 v_ = dmat[r_][i0_ + half_];                           \
            float2 w_ = tw[p_ << s_];                                    \
            dmat[r_][i0_]          = cadd(u_, v_);                       \
            dmat[r_][i0_ + half_]  = cmul(csub(u_, v_), w_);             \
        }                                                                \
    }                                                                    \
    __syncthreads();

#define FFT_DIT_INV(dmat)                                                \
    for (int s_ = 0; s_ < 8; s_++) {                                     \
        __syncthreads();                                                 \
        int half_ = 1 << s_;                                             \
        for (int q_ = threadIdx.x; q_ < 2048; q_ += 256) {               \
            int r_ = q_ >> 7, j_ = q_ & 127;                             \
            int p_ = j_ & (half_ - 1);                                   \
            int i0_ = ((j_ >> s_) << (s_ + 1)) + p_;                     \
            float2 w_ = tw[p_ << (7 - s_)];                              \
            w_.y = -w_.y;                                                \
            float2 t_ = cmul(dmat[r_][i0_ + half_], w_);                 \
            float2 u_ = dmat[r_][i0_];                                   \
            dmat[r_][i0_]         = cadd(u_, t_);                        \
            dmat[r_][i0_ + half_] = csub(u_, t_);                        \
        }                                                                \
    }                                                                    \
    __syncthreads();

// ---------------- encoder / decoder ----------------
__global__ void enc_kernel(const float* __restrict__ x, const float* __restrict__ w,
                           const float* __restrict__ bias, const float* __restrict__ pos,
                           float* __restrict__ h)
{
    int idx = blockIdx.x * 256 + threadIdx.x;
    if (idx >= NB * DIM * HW) return;
    int p = idx & (HW - 1);
    int o = (idx >> 16) & (DIM - 1);
    int b = idx >> 23;
    float x0 = x[(size_t)(b * 2 + 0) * HW + p];
    float x1 = x[(size_t)(b * 2 + 1) * HW + p];
    float v = (w[o * 2] * x0 + w[o * 2 + 1] * x1 + bias[o]) * 8.0f
              + pos[(size_t)o * HW + p];
    h[idx] = v;
}

__global__ void dec_kernel(const float* __restrict__ h, const float* __restrict__ w,
                           const float* __restrict__ bias, float* __restrict__ out)
{
    int idx = blockIdx.x * 256 + threadIdx.x;
    if (idx >= NB * HW) return;
    int p = idx & (HW - 1);
    int b = idx >> 16;
    const float* hb = h + (size_t)b * DIM * HW + p;
    float a0 = 0.f, a1 = 0.f;
#pragma unroll 4
    for (int c = 0; c < DIM; c++) {
        float hv = hb[(size_t)c * HW];
        a0 += w[c] * hv;
        a1 += w[DIM + c] * hv;
    }
    out[(size_t)(b * 2 + 0) * HW + p] = (a0 + bias[0]) * 0.125f;
    out[(size_t)(b * 2 + 1) * HW + p] = (a1 + bias[1]) * 0.125f;
}

// ---------------- per-layer filter precompute (bit-reversed ky order) ----------------
__global__ void prep_filt(const float* __restrict__ mags, const float* __restrict__ phases,
                          float2* __restrict__ filt)
{
    int idx = blockIdx.x * 256 + threadIdx.x;
    if (idx >= DIM * HH * WHF) return;
    int kx = idx % WHF;
    int ky = (idx / WHF) % HH;
    int c  = idx / (WHF * HH);
    int kyp = (ky <= 128) ? ky : (256 - ky);
    float2 o = make_float2(0.f, 0.f);
    if (kx * kx + kyp * kyp <= 16384) {
        float m  = mags[idx];
        float ph = phases[idx];
        float sig = 1.0f / (1.0f + __expf(-m));
        float s, co;
        sincosf(ph, &s, &co);
        float sc = sig * (1.0f / 65536.0f);
        o = make_float2(sc * co, sc * s);
    }
    filt[(size_t)c * (WHF * 256) + (size_t)kx * 256 + brev8(ky)] = o;
}

// ---------------- FFT A: forward real row FFT ----------------
__global__ void fft_row_fwd(const float* __restrict__ z, float2* __restrict__ xf)
{
    __shared__ float2 d[16][256];
    __shared__ float2 tw[128];
    TW_INIT();
    int img = blockIdx.x;
    int y0  = blockIdx.y * 16;
    const float* src = z + (size_t)img * HW + (size_t)y0 * 256;
    for (int idx = threadIdx.x; idx < 4096; idx += 256)
        d[idx >> 8][idx & 255] = make_float2(src[idx], 0.f);
    FFT_DIF(d);
    float2* dst = xf + (size_t)img * (WHF * 256) + y0;
    for (int idx = threadIdx.x; idx < WHF * 16; idx += 256) {
        int kx = idx >> 4, ry = idx & 15;
        dst[(size_t)kx * 256 + ry] = d[ry][brev8(kx)];
    }
}

// ---------------- FFT B: fused column fwd FFT -> filter -> column inv FFT ----------------
__global__ void fft_col(float2* __restrict__ xf, const float2* __restrict__ filt)
{
    __shared__ float2 d[16][256];
    __shared__ float2 tw[128];
    TW_INIT();
    size_t l0 = (size_t)blockIdx.x * 16;
    float2* src = xf + l0 * 256;
    float2* df = &d[0][0];
    for (int idx = threadIdx.x; idx < 4096; idx += 256)
        df[idx] = src[idx];
    FFT_DIF(d);
    for (int idx = threadIdx.x; idx < 4096; idx += 256) {
        int r = idx >> 8;
        size_t fl = ((l0 + r) % (size_t)(DIM * WHF)) * 256;
        float2 f = filt[fl + (idx & 255)];
        df[idx] = cmul(df[idx], f);
    }
    FFT_DIT_INV(d);
    for (int idx = threadIdx.x; idx < 4096; idx += 256)
        src[idx] = df[idx];
}

// ---------------- FFT C: inverse row FFT (c2r) ----------------
__global__ void fft_row_inv(const float2* __restrict__ xf, float* __restrict__ z)
{
    __shared__ float2 d[16][256];
    __shared__ float2 tw[128];
    TW_INIT();
    int img = blockIdx.x;
    int y0  = blockIdx.y * 16;
    const float2* src = xf + (size_t)img * (WHF * 256) + y0;
    for (int idx = threadIdx.x; idx < WHF * 16; idx += 256) {
        int kx = idx >> 4, ry = idx & 15;
        d[ry][brev8(kx)] = src[(size_t)kx * 256 + ry];
    }
    __syncthreads();
    for (int q = threadIdx.x; q < 16 * 127; q += 256) {
        int r = q / 127;
        int k = 129 + (q % 127);
        float2 v = d[r][brev8(256 - k)];
        d[r][brev8(k)] = make_float2(v.x, -v.y);
    }
    FFT_DIT_INV(d);
    float* dst = z + (size_t)img * HW + (size_t)y0 * 256;
    for (int idx = threadIdx.x; idx < 4096; idx += 256)
        dst[idx] = d[idx >> 8][idx & 255].x;
}

// ---------------- launch ----------------
extern "C" void kernel_launch(void* const* d_in, const int* in_sizes, int n_in,
                              void* d_out, int out_size)
{
    const float* x      = (const float*)d_in[0];
    const float* enc_w  = (const float*)d_in[1];
    const float* enc_b  = (const float*)d_in[2];
    const float* pos    = (const float*)d_in[3];
    const float* w1     = (const float*)d_in[4];
    const float* b1     = (const float*)d_in[5];
    const float* w2     = (const float*)d_in[6];
    const float* b2     = (const float*)d_in[7];
    const float* mags   = (const float*)d_in[8];
    const float* phases = (const float*)d_in[9];
    const float* oxw    = (const float*)d_in[10];
    const float* oxb    = (const float*)d_in[11];
    const float* dw     = (const float*)d_in[12];
    const float* db     = (const float*)d_in[13];
    float* out = (float*)d_out;

    float  *h, *y, *z;
    float2 *xf, *ft;
    cudaGetSymbolAddress((void**)&h,  g_h);
    cudaGetSymbolAddress((void**)&y,  g_y);
    cudaGetSymbolAddress((void**)&z,  g_z);
    cudaGetSymbolAddress((void**)&xf, g_xf);
    cudaGetSymbolAddress((void**)&ft, g_filt);

    enc_kernel<<<(NB * DIM * HW + 255) / 256, 256>>>(x, enc_w, enc_b, pos, h);

    const size_t specL = (size_t)DIM * HH * WHF;
    for (int i = 0; i < NLAYERS; i++) {
        prep_filt<<<(int)((specL + 255) / 256), 256>>>(mags + i * specL, phases + i * specL, ft);

        // y = silu(W1 @ h + b1)    (M=512, K=128)
        gemm_mma<128, 1><<<dim3(512, 4, NB), 256>>>(w1 + (size_t)i * HID * DIM, h, b1 + i * HID, y, HID);
        // z = W2 @ y + b2          (M=128, K=512)
        gemm_mma<512, 0><<<dim3(512, 1, NB), 256>>>(w2 + (size_t)i * DIM * HID, y, b2 + i * DIM, z, DIM);

        fft_row_fwd<<<dim3(NB * DIM, 16), 256>>>(z, xf);
        fft_col<<<(NB * DIM * WHF) / 16, 256>>>(xf, ft);
        fft_row_inv<<<dim3(NB * DIM, 16), 256>>>(xf, z);

        // h += OXO @ z + b         (M=128, K=128)
        gemm_mma<128, 2><<<dim3(512, 1, NB), 256>>>(oxw + (size_t)i * DIM * DIM, z, oxb + i * DIM, h, DIM);
    }

    dec_kernel<<<(NB * HW + 255) / 256, 256>>>(h, dw, db, out);
}

// round 7
// speedup vs baseline: 1.2192x; 1.0199x over previous
#include <cuda_runtime.h>
#include <cuda_bf16.h>
#include <math.h>
#include <stdint.h>

#define HH   256
#define HW   65536
#define WHF  129
#define DIM  128
#define HID  512
#define NB   4
#define NLAYERS 4

typedef __nv_bfloat16 bf16;

// ---------------- scratch (device globals) ----------------
__device__ float  g_h[(size_t)NB * DIM * HW];          // 134 MB  residual [b][c][p]
__device__ float  g_z[(size_t)NB * DIM * HW];          // 134 MB  fft input
__device__ float2 g_xf[(size_t)NB * DIM * WHF * 256];  // 135 MB
__device__ float2 g_filt[(size_t)DIM * WHF * 256];     // 34 MB
__device__ bf16   g_h16h[(size_t)NB * DIM * HW];       // 67 MB
__device__ bf16   g_h16l[(size_t)NB * DIM * HW];
__device__ bf16   g_y16h[(size_t)NB * HID * HW];       // 268 MB
__device__ bf16   g_y16l[(size_t)NB * HID * HW];
__device__ bf16   g_z16h[(size_t)NB * DIM * HW];
__device__ bf16   g_z16l[(size_t)NB * DIM * HW];
__device__ bf16   g_w1h[(size_t)NLAYERS * HID * DIM], g_w1l[(size_t)NLAYERS * HID * DIM];
__device__ bf16   g_w2h[(size_t)NLAYERS * DIM * HID], g_w2l[(size_t)NLAYERS * DIM * HID];
__device__ bf16   g_oxh[(size_t)NLAYERS * DIM * DIM], g_oxl[(size_t)NLAYERS * DIM * DIM];

// ---------------- helpers ----------------
__device__ __forceinline__ int brev8(int x) { return (int)(__brev((unsigned)x) >> 24); }
__device__ __forceinline__ float2 cadd(float2 a, float2 b){ return make_float2(a.x+b.x, a.y+b.y); }
__device__ __forceinline__ float2 csub(float2 a, float2 b){ return make_float2(a.x-b.x, a.y-b.y); }
__device__ __forceinline__ float2 cmul(float2 a, float2 b){
    return make_float2(a.x*b.x - a.y*b.y, a.x*b.y + a.y*b.x);
}
__device__ __forceinline__ uint32_t smem_u32(const void* p) {
    uint32_t a;
    asm("{ .reg .u64 t; cvta.to.shared.u64 t, %1; cvt.u32.u64 %0, t; }" : "=r"(a) : "l"(p));
    return a;
}
__device__ __forceinline__ uint32_t pack_hi(float a, float b) {
    return ((uint32_t)__bfloat16_as_ushort(__float2bfloat16(b)) << 16)
         |  (uint32_t)__bfloat16_as_ushort(__float2bfloat16(a));
}
__device__ __forceinline__ uint32_t pack_lo(float a, float b) {
    float ra = a - __bfloat162float(__float2bfloat16(a));
    float rb = b - __bfloat162float(__float2bfloat16(b));
    return ((uint32_t)__bfloat16_as_ushort(__float2bfloat16(rb)) << 16)
         |  (uint32_t)__bfloat16_as_ushort(__float2bfloat16(ra));
}

// ================= mma.sync primitives =================
__device__ __forceinline__ void ldsm4(uint32_t* r, uint32_t addr) {
    asm volatile("ldmatrix.sync.aligned.m8n8.x4.shared.b16 {%0,%1,%2,%3}, [%4];"
                 : "=r"(r[0]), "=r"(r[1]), "=r"(r[2]), "=r"(r[3]) : "r"(addr));
}
__device__ __forceinline__ void ldsm4t(uint32_t* r, uint32_t addr) {
    asm volatile("ldmatrix.sync.aligned.m8n8.x4.trans.shared.b16 {%0,%1,%2,%3}, [%4];"
                 : "=r"(r[0]), "=r"(r[1]), "=r"(r[2]), "=r"(r[3]) : "r"(addr));
}
__device__ __forceinline__ void mma16816(float* c, const uint32_t* a, const uint32_t* b) {
    asm volatile(
        "mma.sync.aligned.m16n8k16.row.col.f32.bf16.bf16.f32 "
        "{%0,%1,%2,%3}, {%4,%5,%6,%7}, {%8,%9}, {%0,%1,%2,%3};"
        : "+f"(c[0]), "+f"(c[1]), "+f"(c[2]), "+f"(c[3])
        : "r"(a[0]), "r"(a[1]), "r"(a[2]), "r"(a[3]), "r"(b[0]), "r"(b[1]));
}
__device__ __forceinline__ void cp16(uint32_t dst, const void* src) {
    asm volatile("cp.async.cg.shared.global [%0], [%1], 16;" :: "r"(dst), "l"(src));
}

// ================= pipelined bf16 tensor-core GEMM =================
// C[m][n] = sum_k A[m][k]*B[k][n] (+bias/epi).  A: weights bf16 hi/lo; B: act bf16 hi/lo.
// EPI: 0 = bias -> fp32 Cf;  1 = bias+silu -> split Ch/Cl;  2 = bias+residual(Cf) -> Cf + Ch/Cl
template <int K, int M, int EPI>
__global__ void __launch_bounds__(256, 1)
gemm_mma(const bf16* __restrict__ Ah, const bf16* __restrict__ Al,
         const bf16* __restrict__ Bh, const bf16* __restrict__ Bl,
         const float* __restrict__ bias,
         float* __restrict__ Cf, bf16* __restrict__ Ch, bf16* __restrict__ Cl)
{
    constexpr int NC = K / 32;
    extern __shared__ uint8_t smem[];                // 3 stages x 32KB
    uint32_t sbase = smem_u32(smem);

    int tid  = threadIdx.x;
    int lane = tid & 31;
    int warp = tid >> 5;
    int wm = warp >> 1, wn = warp & 1;

    const bf16* Ahp = Ah + (size_t)blockIdx.y * 128 * K;
    const bf16* Alp = Al + (size_t)blockIdx.y * 128 * K;
    const bf16* Bhp = Bh + (size_t)blockIdx.z * K * HW + blockIdx.x * 128;
    const bf16* Blp = Bl + (size_t)blockIdx.z * K * HW + blockIdx.x * 128;

    // decode per-thread copy slots: id = tid + it*256; r2: 0=Ah 1=Al 2=Bh 3=Bl
    auto issue = [&](int c) {
        int k0 = c * 32;
        uint32_t sst = sbase + (c % 3) * 32768;
#pragma unroll
        for (int it = 0; it < 8; it++) {
            int id = tid + it * 256;
            int r2 = id >> 9, g = id & 511, tile = g >> 5, line = g & 31;
            const bf16* src;
            if (r2 < 2) {
                int m  = ((tile >> 1) << 4) + (line & 15);
                int gg = ((tile & 1) << 1) + (line >> 4);
                src = (r2 == 0 ? Ahp : Alp) + (size_t)m * K + k0 + gg * 8;
            } else {
                int k  = ((tile >> 3) << 4) + (line & 15);
                int gn = ((tile & 7) << 1) + (line >> 4);
                src = (r2 == 2 ? Bhp : Blp) + (size_t)(k0 + k) * HW + gn * 8;
            }
            cp16(sst + (r2 << 13) + ((tile * 32 + line) << 4), src);
        }
        asm volatile("cp.async.commit_group;" ::: "memory");
    };

    float acc[2][8][4] = {};

    issue(0);
    if (NC > 1) issue(1);

    for (int c = 0; c < NC; c++) {
        // Drain so that group c is COMPLETE. On the last iteration the only
        // pending group is c itself, so we must wait for 0 pending groups.
        if (c + 1 < NC) {
            asm volatile("cp.async.wait_group 1;" ::: "memory");
        } else {
            asm volatile("cp.async.wait_group 0;" ::: "memory");
        }
        __syncthreads();
        uint32_t st = sbase + (c % 3) * 32768;
#pragma unroll
        for (int kb = 0; kb < 2; kb++) {
            uint32_t ah[2][4], al[2][4], bh[4][4], bl[4][4];
#pragma unroll
            for (int i = 0; i < 2; i++) {
                uint32_t ad = st + (((wm * 2 + i) * 2 + kb) << 9) + lane * 16;
                ldsm4(ah[i], ad);
                ldsm4(al[i], ad + 8192);
            }
#pragma unroll
            for (int r = 0; r < 4; r++) {
                uint32_t bd = st + 16384 + ((kb * 8 + wn * 4 + r) << 9) + lane * 16;
                ldsm4t(bh[r], bd);
                ldsm4t(bl[r], bd + 8192);
            }
#pragma unroll
            for (int i = 0; i < 2; i++)
#pragma unroll
                for (int j = 0; j < 8; j++) {
                    const uint32_t* bhp = &bh[j >> 1][(j & 1) * 2];
                    const uint32_t* blp = &bl[j >> 1][(j & 1) * 2];
                    mma16816(acc[i][j], ah[i], bhp);
                    mma16816(acc[i][j], ah[i], blp);
                    mma16816(acc[i][j], al[i], bhp);
                }
        }
        __syncthreads();
        if (c + 2 < NC) issue(c + 2);
    }

    // ---- epilogue ----
    int g = lane >> 2;
    int mb0   = blockIdx.y * 128 + wm * 32;
    int nbase = blockIdx.x * 128 + wn * 64 + (lane & 3) * 2;
    size_t batch = (size_t)blockIdx.z * M * HW;
#pragma unroll
    for (int i = 0; i < 2; i++) {
        int r0 = mb0 + i * 16 + g;
        float bi0 = bias[r0], bi1 = bias[r0 + 8];
        size_t o0 = batch + (size_t)r0 * HW + nbase;
        size_t o1 = o0 + (size_t)8 * HW;
#pragma unroll
        for (int j = 0; j < 8; j++) {
            float v0 = acc[i][j][0] + bi0, v1 = acc[i][j][1] + bi0;
            float v2 = acc[i][j][2] + bi1, v3 = acc[i][j][3] + bi1;
            if (EPI == 1) {
                v0 = v0 / (1.f + __expf(-v0)); v1 = v1 / (1.f + __expf(-v1));
                v2 = v2 / (1.f + __expf(-v2)); v3 = v3 / (1.f + __expf(-v3));
            }
            if (EPI == 2) {
                float2 r0f = *(float2*)(Cf + o0 + j * 8);
                float2 r1f = *(float2*)(Cf + o1 + j * 8);
                v0 += r0f.x; v1 += r0f.y; v2 += r1f.x; v3 += r1f.y;
            }
            if (EPI == 0 || EPI == 2) {
                *(float2*)(Cf + o0 + j * 8) = make_float2(v0, v1);
                *(float2*)(Cf + o1 + j * 8) = make_float2(v2, v3);
            }
            if (EPI == 1 || EPI == 2) {
                *(uint32_t*)(Ch + o0 + j * 8) = pack_hi(v0, v1);
                *(uint32_t*)(Cl + o0 + j * 8) = pack_lo(v0, v1);
                *(uint32_t*)(Ch + o1 + j * 8) = pack_hi(v2, v3);
                *(uint32_t*)(Cl + o1 + j * 8) = pack_lo(v2, v3);
            }
        }
    }
}

// ---------------- weight split ----------------
__global__ void wsplit(const float* __restrict__ w, bf16* __restrict__ wh,
                       bf16* __restrict__ wl, int n)
{
    int i = blockIdx.x * 256 + threadIdx.x;
    if (i >= n) return;
    float v = w[i];
    bf16 h = __float2bfloat16(v);
    wh[i] = h;
    wl[i] = __float2bfloat16(v - __bfloat162float(h));
}

// ---------------- FFT blocks ----------------
#define TW_INIT()                                                        \
    do { if (threadIdx.x < 128) {                                        \
        float s_, c_;                                                    \
        sincospif(-(float)threadIdx.x / 128.0f, &s_, &c_);               \
        tw[threadIdx.x] = make_float2(c_, s_);                           \
    } } while (0)

#define FFT_DIF(dmat)                                                    \
    for (int s_ = 0; s_ < 8; s_++) {                                     \
        __syncthreads();                                                 \
        int half_ = 128 >> s_;                                           \
        for (int q_ = threadIdx.x; q_ < 2048; q_ += 256) {               \
            int r_ = q_ >> 7, j_ = q_ & 127;                             \
            int p_ = j_ & (half_ - 1);                                   \
            int i0_ = ((j_ >> (7 - s_)) << (8 - s_)) + p_;               \
            float2 u_ = dmat[r_][i0_];                                   \
            float2 v_ = dmat[r_][i0_ + half_];                           \
            float2 w_ = tw[p_ << s_];                                    \
            dmat[r_][i0_]          = cadd(u_, v_);                       \
            dmat[r_][i0_ + half_]  = cmul(csub(u_, v_), w_);             \
        }                                                                \
    }                                                                    \
    __syncthreads();

#define FFT_DIT_INV(dmat)                                                \
    for (int s_ = 0; s_ < 8; s_++) {                                     \
        __syncthreads();                                                 \
        int half_ = 1 << s_;                                             \
        for (int q_ = threadIdx.x; q_ < 2048; q_ += 256) {               \
            int r_ = q_ >> 7, j_ = q_ & 127;                             \
            int p_ = j_ & (half_ - 1);                                   \
            int i0_ = ((j_ >> s_) << (s_ + 1)) + p_;                     \
            float2 w_ = tw[p_ << (7 - s_)];                              \
            w_.y = -w_.y;                                                \
            float2 t_ = cmul(dmat[r_][i0_ + half_], w_);                 \
            float2 u_ = dmat[r_][i0_];                                   \
            dmat[r_][i0_]         = cadd(u_, t_);                        \
            dmat[r_][i0_ + half_] = csub(u_, t_);                        \
        }                                                                \
    }                                                                    \
    __syncthreads();

__global__ void fft_row_fwd(const float* __restrict__ z, float2* __restrict__ xf)
{
    __shared__ float2 d[16][256];
    __shared__ float2 tw[128];
    TW_INIT();
    int img = blockIdx.x;
    int y0  = blockIdx.y * 16;
    const float* src = z + (size_t)img * HW + (size_t)y0 * 256;
    for (int idx = threadIdx.x; idx < 4096; idx += 256)
        d[idx >> 8][idx & 255] = make_float2(src[idx], 0.f);
    FFT_DIF(d);
    float2* dst = xf + (size_t)img * (WHF * 256) + y0;
    for (int idx = threadIdx.x; idx < WHF * 16; idx += 256) {
        int kx = idx >> 4, ry = idx & 15;
        dst[(size_t)kx * 256 + ry] = d[ry][brev8(kx)];
    }
}

__global__ void fft_col(float2* __restrict__ xf, const float2* __restrict__ filt)
{
    __shared__ float2 d[16][256];
    __shared__ float2 tw[128];
    TW_INIT();
    size_t l0 = (size_t)blockIdx.x * 16;
    float2* src = xf + l0 * 256;
    float2* df = &d[0][0];
    for (int idx = threadIdx.x; idx < 4096; idx += 256)
        df[idx] = src[idx];
    FFT_DIF(d);
    for (int idx = threadIdx.x; idx < 4096; idx += 256) {
        int r = idx >> 8;
        size_t fl = ((l0 + r) % (size_t)(DIM * WHF)) * 256;
        float2 f = filt[fl + (idx & 255)];
        df[idx] = cmul(df[idx], f);
    }
    FFT_DIT_INV(d);
    for (int idx = threadIdx.x; idx < 4096; idx += 256)
        src[idx] = df[idx];
}

__global__ void fft_row_inv(const float2* __restrict__ xf,
                            bf16* __restrict__ zh, bf16* __restrict__ zl)
{
    __shared__ float2 d[16][256];
    __shared__ float2 tw[128];
    TW_INIT();
    int img = blockIdx.x;
    int y0  = blockIdx.y * 16;
    const float2* src = xf + (size_t)img * (WHF * 256) + y0;
    for (int idx = threadIdx.x; idx < WHF * 16; idx += 256) {
        int kx = idx >> 4, ry = idx & 15;
        d[ry][brev8(kx)] = src[(size_t)kx * 256 + ry];
    }
    __syncthreads();
    for (int q = threadIdx.x; q < 16 * 127; q += 256) {
        int r = q / 127;
        int k = 129 + (q % 127);
        float2 v = d[r][brev8(256 - k)];
        d[r][brev8(k)] = make_float2(v.x, -v.y);
    }
    FFT_DIT_INV(d);
    size_t o = (size_t)img * HW + (size_t)y0 * 256;
    for (int idx = threadIdx.x; idx < 2048; idx += 256) {
        float v0 = d[idx >> 7][(idx & 127) * 2].x;
        float v1 = d[idx >> 7][(idx & 127) * 2 + 1].x;
        *(uint32_t*)(zh + o + idx * 2) = pack_hi(v0, v1);
        *(uint32_t*)(zl + o + idx * 2) = pack_lo(v0, v1);
    }
}

// ---------------- enc / dec / filter ----------------
__global__ void enc_kernel(const float* __restrict__ x, const float* __restrict__ w,
                           const float* __restrict__ bias, const float* __restrict__ pos,
                           float* __restrict__ h, bf16* __restrict__ hh, bf16* __restrict__ hl)
{
    int idx = blockIdx.x * 256 + threadIdx.x;
    if (idx >= NB * DIM * HW / 2) return;
    int e = idx * 2;
    int p = e & (HW - 1);
    int o = (e >> 16) & (DIM - 1);
    int b = e >> 23;
    float x0 = x[(size_t)(b * 2 + 0) * HW + p];
    float x1 = x[(size_t)(b * 2 + 1) * HW + p];
    float x0b = x[(size_t)(b * 2 + 0) * HW + p + 1];
    float x1b = x[(size_t)(b * 2 + 1) * HW + p + 1];
    float w0 = w[o * 2], w1 = w[o * 2 + 1], bb = bias[o];
    float v0 = (w0 * x0 + w1 * x1 + bb) * 8.0f + pos[(size_t)o * HW + p];
    float v1 = (w0 * x0b + w1 * x1b + bb) * 8.0f + pos[(size_t)o * HW + p + 1];
    *(float2*)(h + e) = make_float2(v0, v1);
    *(uint32_t*)(hh + e) = pack_hi(v0, v1);
    *(uint32_t*)(hl + e) = pack_lo(v0, v1);
}

__global__ void dec_kernel(const float* __restrict__ h, const float* __restrict__ w,
                           const float* __restrict__ bias, float* __restrict__ out)
{
    int idx = blockIdx.x * 256 + threadIdx.x;
    if (idx >= NB * HW) return;
    int p = idx & (HW - 1);
    int b = idx >> 16;
    const float* hb = h + (size_t)b * DIM * HW + p;
    float a0 = 0.f, a1 = 0.f;
#pragma unroll 4
    for (int c = 0; c < DIM; c++) {
        float hv = hb[(size_t)c * HW];
        a0 += w[c] * hv;
        a1 += w[DIM + c] * hv;
    }
    out[(size_t)(b * 2 + 0) * HW + p] = (a0 + bias[0]) * 0.125f;
    out[(size_t)(b * 2 + 1) * HW + p] = (a1 + bias[1]) * 0.125f;
}

__global__ void prep_filt(const float* __restrict__ mags, const float* __restrict__ phases,
                          float2* __restrict__ filt)
{
    int idx = blockIdx.x * 256 + threadIdx.x;
    if (idx >= DIM * HH * WHF) return;
    int kx = idx % WHF;
    int ky = (idx / WHF) % HH;
    int c  = idx / (WHF * HH);
    int kyp = (ky <= 128) ? ky : (256 - ky);
    float2 o = make_float2(0.f, 0.f);
    if (kx * kx + kyp * kyp <= 16384) {
        float sig = 1.0f / (1.0f + __expf(-mags[idx]));
        float s, co;
        sincosf(phases[idx], &s, &co);
        float sc = sig * (1.0f / 65536.0f);
        o = make_float2(sc * co, sc * s);
    }
    filt[(size_t)c * (WHF * 256) + (size_t)kx * 256 + brev8(ky)] = o;
}

// ---------------- launch ----------------
extern "C" void kernel_launch(void* const* d_in, const int* in_sizes, int n_in,
                              void* d_out, int out_size)
{
    const float* x      = (const float*)d_in[0];
    const float* enc_w  = (const float*)d_in[1];
    const float* enc_b  = (const float*)d_in[2];
    const float* pos    = (const float*)d_in[3];
    const float* w1     = (const float*)d_in[4];
    const float* b1     = (const float*)d_in[5];
    const float* w2     = (const float*)d_in[6];
    const float* b2     = (const float*)d_in[7];
    const float* mags   = (const float*)d_in[8];
    const float* phases = (const float*)d_in[9];
    const float* oxw    = (const float*)d_in[10];
    const float* oxb    = (const float*)d_in[11];
    const float* dw     = (const float*)d_in[12];
    const float* db     = (const float*)d_in[13];
    float* out = (float*)d_out;

    float *h, *z;
    float2 *xf, *ft;
    bf16 *hh, *hl, *yh, *yl, *zh, *zl, *w1h, *w1l, *w2h, *w2l, *oxh, *oxl;
    cudaGetSymbolAddress((void**)&h,   g_h);
    cudaGetSymbolAddress((void**)&z,   g_z);
    cudaGetSymbolAddress((void**)&xf,  g_xf);
    cudaGetSymbolAddress((void**)&ft,  g_filt);
    cudaGetSymbolAddress((void**)&hh,  g_h16h);
    cudaGetSymbolAddress((void**)&hl,  g_h16l);
    cudaGetSymbolAddress((void**)&yh,  g_y16h);
    cudaGetSymbolAddress((void**)&yl,  g_y16l);
    cudaGetSymbolAddress((void**)&zh,  g_z16h);
    cudaGetSymbolAddress((void**)&zl,  g_z16l);
    cudaGetSymbolAddress((void**)&w1h, g_w1h);
    cudaGetSymbolAddress((void**)&w1l, g_w1l);
    cudaGetSymbolAddress((void**)&w2h, g_w2h);
    cudaGetSymbolAddress((void**)&w2l, g_w2l);
    cudaGetSymbolAddress((void**)&oxh, g_oxh);
    cudaGetSymbolAddress((void**)&oxl, g_oxl);

    const int SMEM = 3 * 32768;
    static bool attr = false;
    if (!attr) {
        cudaFuncSetAttribute(gemm_mma<128, 512, 1>, cudaFuncAttributeMaxDynamicSharedMemorySize, SMEM);
        cudaFuncSetAttribute(gemm_mma<512, 128, 0>, cudaFuncAttributeMaxDynamicSharedMemorySize, SMEM);
        cudaFuncSetAttribute(gemm_mma<128, 128, 2>, cudaFuncAttributeMaxDynamicSharedMemorySize, SMEM);
        attr = true;
    }

    wsplit<<<(NLAYERS * HID * DIM + 255) / 256, 256>>>(w1, w1h, w1l, NLAYERS * HID * DIM);
    wsplit<<<(NLAYERS * DIM * HID + 255) / 256, 256>>>(w2, w2h, w2l, NLAYERS * DIM * HID);
    wsplit<<<(NLAYERS * DIM * DIM + 255) / 256, 256>>>(oxw, oxh, oxl, NLAYERS * DIM * DIM);

    enc_kernel<<<(NB * DIM * HW / 2 + 255) / 256, 256>>>(x, enc_w, enc_b, pos, h, hh, hl);

    const size_t specL = (size_t)DIM * HH * WHF;
    for (int i = 0; i < NLAYERS; i++) {
        prep_filt<<<(int)((specL + 255) / 256), 256>>>(mags + i * specL, phases + i * specL, ft);

        gemm_mma<128, 512, 1><<<dim3(512, 4, NB), 256, SMEM>>>(
            w1h + (size_t)i * HID * DIM, w1l + (size_t)i * HID * DIM,
            hh, hl, b1 + i * HID, nullptr, yh, yl);
        gemm_mma<512, 128, 0><<<dim3(512, 1, NB), 256, SMEM>>>(
            w2h + (size_t)i * DIM * HID, w2l + (size_t)i * DIM * HID,
            yh, yl, b2 + i * DIM, z, nullptr, nullptr);

        fft_row_fwd<<<dim3(NB * DIM, 16), 256>>>(z, xf);
        fft_col<<<(NB * DIM * WHF) / 16, 256>>>(xf, ft);
        fft_row_inv<<<dim3(NB * DIM, 16), 256>>>(xf, zh, zl);

        gemm_mma<128, 128, 2><<<dim3(512, 1, NB), 256, SMEM>>>(
            oxh + (size_t)i * DIM * DIM, oxl + (size_t)i * DIM * DIM,
            zh, zl, oxb + i * DIM, h, hh, hl);
    }

    dec_kernel<<<(NB * HW + 255) / 256, 256>>>(h, dw, db, out);
}

// round 8
// speedup vs baseline: 1.3639x; 1.1187x over previous
#include <cuda_runtime.h>
#include <cuda_bf16.h>
#include <math.h>
#include <stdint.h>

#define HH   256
#define HW   65536
#define WHF  129
#define DIM  128
#define HID  512
#define NB   4
#define NLAYERS 4

typedef __nv_bfloat16 bf16;

// ---------------- scratch (device globals) ----------------
__device__ float  g_h[(size_t)NB * DIM * HW];          // residual [b][c][p]
__device__ float  g_z[(size_t)NB * DIM * HW];          // fft input
__device__ float2 g_xf[(size_t)NB * DIM * WHF * 256];
__device__ float2 g_filt[(size_t)DIM * WHF * 256];
__device__ bf16   g_h16h[(size_t)NB * DIM * HW];
__device__ bf16   g_h16l[(size_t)NB * DIM * HW];
__device__ bf16   g_y16h[(size_t)NB * HID * HW];
__device__ bf16   g_y16l[(size_t)NB * HID * HW];
__device__ bf16   g_z16h[(size_t)NB * DIM * HW];
__device__ bf16   g_z16l[(size_t)NB * DIM * HW];
__device__ bf16   g_w1h[(size_t)NLAYERS * HID * DIM], g_w1l[(size_t)NLAYERS * HID * DIM];
__device__ bf16   g_w2h[(size_t)NLAYERS * DIM * HID], g_w2l[(size_t)NLAYERS * DIM * HID];
__device__ bf16   g_oxh[(size_t)NLAYERS * DIM * DIM], g_oxl[(size_t)NLAYERS * DIM * DIM];

// ---------------- helpers ----------------
__device__ __forceinline__ int brev8(int x) { return (int)(__brev((unsigned)x) >> 24); }
__device__ __forceinline__ float2 cadd(float2 a, float2 b){ return make_float2(a.x+b.x, a.y+b.y); }
__device__ __forceinline__ float2 csub(float2 a, float2 b){ return make_float2(a.x-b.x, a.y-b.y); }
__device__ __forceinline__ float2 cmul(float2 a, float2 b){
    return make_float2(a.x*b.x - a.y*b.y, a.x*b.y + a.y*b.x);
}
__device__ __forceinline__ uint32_t smem_u32(const void* p) {
    uint32_t a;
    asm("{ .reg .u64 t; cvta.to.shared.u64 t, %1; cvt.u32.u64 %0, t; }" : "=r"(a) : "l"(p));
    return a;
}
__device__ __forceinline__ uint32_t pack_hi(float a, float b) {
    return ((uint32_t)__bfloat16_as_ushort(__float2bfloat16(b)) << 16)
         |  (uint32_t)__bfloat16_as_ushort(__float2bfloat16(a));
}
__device__ __forceinline__ uint32_t pack_lo(float a, float b) {
    float ra = a - __bfloat162float(__float2bfloat16(a));
    float rb = b - __bfloat162float(__float2bfloat16(b));
    return ((uint32_t)__bfloat16_as_ushort(__float2bfloat16(rb)) << 16)
         |  (uint32_t)__bfloat16_as_ushort(__float2bfloat16(ra));
}

// ================= mma.sync primitives =================
__device__ __forceinline__ void ldsm4(uint32_t* r, uint32_t addr) {
    asm volatile("ldmatrix.sync.aligned.m8n8.x4.shared.b16 {%0,%1,%2,%3}, [%4];"
                 : "=r"(r[0]), "=r"(r[1]), "=r"(r[2]), "=r"(r[3]) : "r"(addr));
}
__device__ __forceinline__ void ldsm4t(uint32_t* r, uint32_t addr) {
    asm volatile("ldmatrix.sync.aligned.m8n8.x4.trans.shared.b16 {%0,%1,%2,%3}, [%4];"
                 : "=r"(r[0]), "=r"(r[1]), "=r"(r[2]), "=r"(r[3]) : "r"(addr));
}
__device__ __forceinline__ void mma16816(float* c, const uint32_t* a, const uint32_t* b) {
    asm volatile(
        "mma.sync.aligned.m16n8k16.row.col.f32.bf16.bf16.f32 "
        "{%0,%1,%2,%3}, {%4,%5,%6,%7}, {%8,%9}, {%0,%1,%2,%3};"
        : "+f"(c[0]), "+f"(c[1]), "+f"(c[2]), "+f"(c[3])
        : "r"(a[0]), "r"(a[1]), "r"(a[2]), "r"(a[3]), "r"(b[0]), "r"(b[1]));
}
__device__ __forceinline__ void cp16(uint32_t dst, const void* src) {
    asm volatile("cp.async.cg.shared.global [%0], [%1], 16;" :: "r"(dst), "l"(src));
}

// ================= wide pipelined bf16 tensor-core GEMM =================
// 512 threads, block tile 128m x 256n, warp grid 4x4 (warp = 32m x 64n).
// C[m][n] = sum_k A[m][k]*B[k][n] (+bias/epi).  3-pass compensated bf16.
// EPI: 0 = bias -> fp32 Cf;  1 = bias+silu -> split Ch/Cl;  2 = bias+residual(Cf) -> Cf + Ch/Cl
template <int K, int M, int EPI>
__global__ void __launch_bounds__(512, 1)
gemm_mma(const bf16* __restrict__ Ah, const bf16* __restrict__ Al,
         const bf16* __restrict__ Bh, const bf16* __restrict__ Bl,
         const float* __restrict__ bias,
         float* __restrict__ Cf, bf16* __restrict__ Ch, bf16* __restrict__ Cl)
{
    constexpr int NC = K / 32;
    constexpr int STAGE = 49152;                     // [Ah 8K][Al 8K][Bh 16K][Bl 16K]
    extern __shared__ uint8_t smem[];                // 3 stages
    uint32_t sbase = smem_u32(smem);

    int tid  = threadIdx.x;
    int lane = tid & 31;
    int warp = tid >> 5;
    int wm = warp >> 2, wn = warp & 3;               // 4x4

    const bf16* Ahp = Ah + (size_t)blockIdx.y * 128 * K;
    const bf16* Alp = Al + (size_t)blockIdx.y * 128 * K;
    const bf16* Bhp = Bh + (size_t)blockIdx.z * K * HW + blockIdx.x * 256;
    const bf16* Blp = Bl + (size_t)blockIdx.z * K * HW + blockIdx.x * 256;

    // ---- per-thread copy slots (6 x 16B per stage; pointers advance per chunk) ----
    const bf16* gp[6];
    uint32_t    off[6];
    {
        int tile = tid >> 5, line = tid & 31;
        int am  = ((tile >> 1) << 4) + (line & 15);
        int agg = ((tile & 1) << 1) + (line >> 4);
        size_t aoff = (size_t)am * K + agg * 8;
        gp[0] = Ahp + aoff;  gp[1] = Alp + aoff;
        off[0] = tile * 512 + line * 16;
        off[1] = off[0] + 8192;
        int bk  = line & 15;
        int bgn = (tile & 15) * 2 + (line >> 4);     // n8 index 0..31
        size_t b0 = (size_t)bk * HW + bgn * 8;       // k16 = 0
        size_t b1 = (size_t)(bk + 16) * HW + bgn * 8;// k16 = 1
        gp[2] = Bhp + b0;  gp[3] = Bhp + b1;
        gp[4] = Blp + b0;  gp[5] = Blp + b1;
        off[2] = 16384 + tile * 512 + line * 16;
        off[3] = 16384 + (tile + 16) * 512 + line * 16;
        off[4] = off[2] + 16384;
        off[5] = off[3] + 16384;
    }

    auto issue = [&](int c) {
        uint32_t sst = sbase + (c % 3) * STAGE;
        cp16(sst + off[0], gp[0]);  gp[0] += 32;
        cp16(sst + off[1], gp[1]);  gp[1] += 32;
        cp16(sst + off[2], gp[2]);  gp[2] += (size_t)32 * HW;
        cp16(sst + off[3], gp[3]);  gp[3] += (size_t)32 * HW;
        cp16(sst + off[4], gp[4]);  gp[4] += (size_t)32 * HW;
        cp16(sst + off[5], gp[5]);  gp[5] += (size_t)32 * HW;
        asm volatile("cp.async.commit_group;" ::: "memory");
    };

    float acc[2][8][4] = {};

    issue(0);
    if (NC > 1) issue(1);

    for (int c = 0; c < NC; c++) {
        if (c + 1 < NC) {
            asm volatile("cp.async.wait_group 1;" ::: "memory");
        } else {
            asm volatile("cp.async.wait_group 0;" ::: "memory");
        }
        __syncthreads();
        uint32_t st = sbase + (c % 3) * STAGE;
#pragma unroll
        for (int kb = 0; kb < 2; kb++) {
            uint32_t ah[2][4], al[2][4];
#pragma unroll
            for (int i = 0; i < 2; i++) {
                uint32_t ad = st + ((((wm * 2 + i) * 2) + kb) << 9) + lane * 16;
                ldsm4(ah[i], ad);
                ldsm4(al[i], ad + 8192);
            }
#pragma unroll
            for (int r = 0; r < 4; r++) {
                uint32_t bh[4], bl[4];
                uint32_t bd = st + 16384 + ((kb * 16 + wn * 4 + r) << 9) + lane * 16;
                ldsm4t(bh, bd);
                ldsm4t(bl, bd + 16384);
#pragma unroll
                for (int i = 0; i < 2; i++)
#pragma unroll
                    for (int hh = 0; hh < 2; hh++) {
                        float* a_ = acc[i][r * 2 + hh];
                        mma16816(a_, ah[i], &bh[hh * 2]);
                        mma16816(a_, ah[i], &bl[hh * 2]);
                        mma16816(a_, al[i], &bh[hh * 2]);
                    }
            }
        }
        __syncthreads();
        if (c + 2 < NC) issue(c + 2);
    }

    // ---- epilogue ----
    int g = lane >> 2;
    int mb0   = blockIdx.y * 128 + wm * 32;
    int nbase = blockIdx.x * 256 + wn * 64 + (lane & 3) * 2;
    size_t batch = (size_t)blockIdx.z * M * HW;
#pragma unroll
    for (int i = 0; i < 2; i++) {
        int r0 = mb0 + i * 16 + g;
        float bi0 = bias[r0], bi1 = bias[r0 + 8];
        size_t o0 = batch + (size_t)r0 * HW + nbase;
        size_t o1 = o0 + (size_t)8 * HW;
#pragma unroll
        for (int j = 0; j < 8; j++) {
            float v0 = acc[i][j][0] + bi0, v1 = acc[i][j][1] + bi0;
            float v2 = acc[i][j][2] + bi1, v3 = acc[i][j][3] + bi1;
            if (EPI == 1) {
                v0 = v0 / (1.f + __expf(-v0)); v1 = v1 / (1.f + __expf(-v1));
                v2 = v2 / (1.f + __expf(-v2)); v3 = v3 / (1.f + __expf(-v3));
            }
            if (EPI == 2) {
                float2 r0f = *(float2*)(Cf + o0 + j * 8);
                float2 r1f = *(float2*)(Cf + o1 + j * 8);
                v0 += r0f.x; v1 += r0f.y; v2 += r1f.x; v3 += r1f.y;
            }
            if (EPI == 0 || EPI == 2) {
                *(float2*)(Cf + o0 + j * 8) = make_float2(v0, v1);
                *(float2*)(Cf + o1 + j * 8) = make_float2(v2, v3);
            }
            if (EPI == 1 || EPI == 2) {
                *(uint32_t*)(Ch + o0 + j * 8) = pack_hi(v0, v1);
                *(uint32_t*)(Cl + o0 + j * 8) = pack_lo(v0, v1);
                *(uint32_t*)(Ch + o1 + j * 8) = pack_hi(v2, v3);
                *(uint32_t*)(Cl + o1 + j * 8) = pack_lo(v2, v3);
            }
        }
    }
}

// ---------------- weight split ----------------
__global__ void wsplit(const float* __restrict__ w, bf16* __restrict__ wh,
                       bf16* __restrict__ wl, int n)
{
    int i = blockIdx.x * 256 + threadIdx.x;
    if (i >= n) return;
    float v = w[i];
    bf16 h = __float2bfloat16(v);
    wh[i] = h;
    wl[i] = __float2bfloat16(v - __bfloat162float(h));
}

// ---------------- FFT blocks ----------------
#define TW_INIT()                                                        \
    do { if (threadIdx.x < 128) {                                        \
        float s_, c_;                                                    \
        sincospif(-(float)threadIdx.x / 128.0f, &s_, &c_);               \
        tw[threadIdx.x] = make_float2(c_, s_);                           \
    } } while (0)

#define FFT_DIF(dmat)                                                    \
    for (int s_ = 0; s_ < 8; s_++) {                                     \
        __syncthreads();                                                 \
        int half_ = 128 >> s_;                                           \
        for (int q_ = threadIdx.x; q_ < 2048; q_ += 256) {               \
            int r_ = q_ >> 7, j_ = q_ & 127;                             \
            int p_ = j_ & (half_ - 1);                                   \
            int i0_ = ((j_ >> (7 - s_)) << (8 - s_)) + p_;               \
            float2 u_ = dmat[r_][i0_];                                   \
            float2 v_ = dmat[r_][i0_ + half_];                           \
            float2 w_ = tw[p_ << s_];                                    \
            dmat[r_][i0_]          = cadd(u_, v_);                       \
            dmat[r_][i0_ + half_]  = cmul(csub(u_, v_), w_);             \
        }                                                                \
    }                                                                    \
    __syncthreads();

#define FFT_DIT_INV(dmat)                                                \
    for (int s_ = 0; s_ < 8; s_++) {                                     \
        __syncthreads();                                                 \
        int half_ = 1 << s_;                                             \
        for (int q_ = threadIdx.x; q_ < 2048; q_ += 256) {               \
            int r_ = q_ >> 7, j_ = q_ & 127;                             \
            int p_ = j_ & (half_ - 1);                                   \
            int i0_ = ((j_ >> s_) << (s_ + 1)) + p_;                     \
            float2 w_ = tw[p_ << (7 - s_)];                              \
            w_.y = -w_.y;                                                \
            float2 t_ = cmul(dmat[r_][i0_ + half_], w_);                 \
            float2 u_ = dmat[r_][i0_];                                   \
            dmat[r_][i0_]         = cadd(u_, t_);                        \
            dmat[r_][i0_ + half_] = csub(u_, t_);                        \
        }                                                                \
    }                                                                    \
    __syncthreads();

__global__ void fft_row_fwd(const float* __restrict__ z, float2* __restrict__ xf)
{
    __shared__ float2 d[16][256];
    __shared__ float2 tw[128];
    TW_INIT();
    int img = blockIdx.x;
    int y0  = blockIdx.y * 16;
    const float* src = z + (size_t)img * HW + (size_t)y0 * 256;
    for (int idx = threadIdx.x; idx < 4096; idx += 256)
        d[idx >> 8][idx & 255] = make_float2(src[idx], 0.f);
    FFT_DIF(d);
    float2* dst = xf + (size_t)img * (WHF * 256) + y0;
    for (int idx = threadIdx.x; idx < WHF * 16; idx += 256) {
        int kx = idx >> 4, ry = idx & 15;
        dst[(size_t)kx * 256 + ry] = d[ry][brev8(kx)];
    }
}

__global__ void fft_col(float2* __restrict__ xf, const float2* __restrict__ filt)
{
    __shared__ float2 d[16][256];
    __shared__ float2 tw[128];
    TW_INIT();
    size_t l0 = (size_t)blockIdx.x * 16;
    float2* src = xf + l0 * 256;
    float2* df = &d[0][0];
    for (int idx = threadIdx.x; idx < 4096; idx += 256)
        df[idx] = src[idx];
    FFT_DIF(d);
    for (int idx = threadIdx.x; idx < 4096; idx += 256) {
        int r = idx >> 8;
        size_t fl = ((l0 + r) % (size_t)(DIM * WHF)) * 256;
        float2 f = filt[fl + (idx & 255)];
        df[idx] = cmul(df[idx], f);
    }
    FFT_DIT_INV(d);
    for (int idx = threadIdx.x; idx < 4096; idx += 256)
        src[idx] = df[idx];
}

__global__ void fft_row_inv(const float2* __restrict__ xf,
                            bf16* __restrict__ zh, bf16* __restrict__ zl)
{
    __shared__ float2 d[16][256];
    __shared__ float2 tw[128];
    TW_INIT();
    int img = blockIdx.x;
    int y0  = blockIdx.y * 16;
    const float2* src = xf + (size_t)img * (WHF * 256) + y0;
    for (int idx = threadIdx.x; idx < WHF * 16; idx += 256) {
        int kx = idx >> 4, ry = idx & 15;
        d[ry][brev8(kx)] = src[(size_t)kx * 256 + ry];
    }
    __syncthreads();
    for (int q = threadIdx.x; q < 16 * 127; q += 256) {
        int r = q / 127;
        int k = 129 + (q % 127);
        float2 v = d[r][brev8(256 - k)];
        d[r][brev8(k)] = make_float2(v.x, -v.y);
    }
    FFT_DIT_INV(d);
    size_t o = (size_t)img * HW + (size_t)y0 * 256;
    for (int idx = threadIdx.x; idx < 2048; idx += 256) {
        float v0 = d[idx >> 7][(idx & 127) * 2].x;
        float v1 = d[idx >> 7][(idx & 127) * 2 + 1].x;
        *(uint32_t*)(zh + o + idx * 2) = pack_hi(v0, v1);
        *(uint32_t*)(zl + o + idx * 2) = pack_lo(v0, v1);
    }
}

// ---------------- enc / dec / filter ----------------
__global__ void enc_kernel(const float* __restrict__ x, const float* __restrict__ w,
                           const float* __restrict__ bias, const float* __restrict__ pos,
                           float* __restrict__ h, bf16* __restrict__ hh, bf16* __restrict__ hl)
{
    int idx = blockIdx.x * 256 + threadIdx.x;
    if (idx >= NB * DIM * HW / 2) return;
    int e = idx * 2;
    int p = e & (HW - 1);
    int o = (e >> 16) & (DIM - 1);
    int b = e >> 23;
    float x0 = x[(size_t)(b * 2 + 0) * HW + p];
    float x1 = x[(size_t)(b * 2 + 1) * HW + p];
    float x0b = x[(size_t)(b * 2 + 0) * HW + p + 1];
    float x1b = x[(size_t)(b * 2 + 1) * HW + p + 1];
    float w0 = w[o * 2], w1 = w[o * 2 + 1], bb = bias[o];
    float v0 = (w0 * x0 + w1 * x1 + bb) * 8.0f + pos[(size_t)o * HW + p];
    float v1 = (w0 * x0b + w1 * x1b + bb) * 8.0f + pos[(size_t)o * HW + p + 1];
    *(float2*)(h + e) = make_float2(v0, v1);
    *(uint32_t*)(hh + e) = pack_hi(v0, v1);
    *(uint32_t*)(hl + e) = pack_lo(v0, v1);
}

__global__ void dec_kernel(const float* __restrict__ h, const float* __restrict__ w,
                           const float* __restrict__ bias, float* __restrict__ out)
{
    int idx = blockIdx.x * 256 + threadIdx.x;
    if (idx >= NB * HW) return;
    int p = idx & (HW - 1);
    int b = idx >> 16;
    const float* hb = h + (size_t)b * DIM * HW + p;
    float a0 = 0.f, a1 = 0.f;
#pragma unroll 4
    for (int c = 0; c < DIM; c++) {
        float hv = hb[(size_t)c * HW];
        a0 += w[c] * hv;
        a1 += w[DIM + c] * hv;
    }
    out[(size_t)(b * 2 + 0) * HW + p] = (a0 + bias[0]) * 0.125f;
    out[(size_t)(b * 2 + 1) * HW + p] = (a1 + bias[1]) * 0.125f;
}

__global__ void prep_filt(const float* __restrict__ mags, const float* __restrict__ phases,
                          float2* __restrict__ filt)
{
    int idx = blockIdx.x * 256 + threadIdx.x;
    if (idx >= DIM * HH * WHF) return;
    int kx = idx % WHF;
    int ky = (idx / WHF) % HH;
    int c  = idx / (WHF * HH);
    int kyp = (ky <= 128) ? ky : (256 - ky);
    float2 o = make_float2(0.f, 0.f);
    if (kx * kx + kyp * kyp <= 16384) {
        float sig = 1.0f / (1.0f + __expf(-mags[idx]));
        float s, co;
        sincosf(phases[idx], &s, &co);
        float sc = sig * (1.0f / 65536.0f);
        o = make_float2(sc * co, sc * s);
    }
    filt[(size_t)c * (WHF * 256) + (size_t)kx * 256 + brev8(ky)] = o;
}

// ---------------- launch ----------------
extern "C" void kernel_launch(void* const* d_in, const int* in_sizes, int n_in,
                              void* d_out, int out_size)
{
    const float* x      = (const float*)d_in[0];
    const float* enc_w  = (const float*)d_in[1];
    const float* enc_b  = (const float*)d_in[2];
    const float* pos    = (const float*)d_in[3];
    const float* w1     = (const float*)d_in[4];
    const float* b1     = (const float*)d_in[5];
    const float* w2     = (const float*)d_in[6];
    const float* b2     = (const float*)d_in[7];
    const float* mags   = (const float*)d_in[8];
    const float* phases = (const float*)d_in[9];
    const float* oxw    = (const float*)d_in[10];
    const float* oxb    = (const float*)d_in[11];
    const float* dw     = (const float*)d_in[12];
    const float* db     = (const float*)d_in[13];
    float* out = (float*)d_out;

    float *h, *z;
    float2 *xf, *ft;
    bf16 *hh, *hl, *yh, *yl, *zh, *zl, *w1h, *w1l, *w2h, *w2l, *oxh, *oxl;
    cudaGetSymbolAddress((void**)&h,   g_h);
    cudaGetSymbolAddress((void**)&z,   g_z);
    cudaGetSymbolAddress((void**)&xf,  g_xf);
    cudaGetSymbolAddress((void**)&ft,  g_filt);
    cudaGetSymbolAddress((void**)&hh,  g_h16h);
    cudaGetSymbolAddress((void**)&hl,  g_h16l);
    cudaGetSymbolAddress((void**)&yh,  g_y16h);
    cudaGetSymbolAddress((void**)&yl,  g_y16l);
    cudaGetSymbolAddress((void**)&zh,  g_z16h);
    cudaGetSymbolAddress((void**)&zl,  g_z16l);
    cudaGetSymbolAddress((void**)&w1h, g_w1h);
    cudaGetSymbolAddress((void**)&w1l, g_w1l);
    cudaGetSymbolAddress((void**)&w2h, g_w2h);
    cudaGetSymbolAddress((void**)&w2l, g_w2l);
    cudaGetSymbolAddress((void**)&oxh, g_oxh);
    cudaGetSymbolAddress((void**)&oxl, g_oxl);

    const int SMEM = 3 * 49152;                      // 144 KB
    static bool attr = false;
    if (!attr) {
        cudaFuncSetAttribute(gemm_mma<128, 512, 1>, cudaFuncAttributeMaxDynamicSharedMemorySize, SMEM);
        cudaFuncSetAttribute(gemm_mma<512, 128, 0>, cudaFuncAttributeMaxDynamicSharedMemorySize, SMEM);
        cudaFuncSetAttribute(gemm_mma<128, 128, 2>, cudaFuncAttributeMaxDynamicSharedMemorySize, SMEM);
        attr = true;
    }

    wsplit<<<(NLAYERS * HID * DIM + 255) / 256, 256>>>(w1, w1h, w1l, NLAYERS * HID * DIM);
    wsplit<<<(NLAYERS * DIM * HID + 255) / 256, 256>>>(w2, w2h, w2l, NLAYERS * DIM * HID);
    wsplit<<<(NLAYERS * DIM * DIM + 255) / 256, 256>>>(oxw, oxh, oxl, NLAYERS * DIM * DIM);

    enc_kernel<<<(NB * DIM * HW / 2 + 255) / 256, 256>>>(x, enc_w, enc_b, pos, h, hh, hl);

    const size_t specL = (size_t)DIM * HH * WHF;
    for (int i = 0; i < NLAYERS; i++) {
        prep_filt<<<(int)((specL + 255) / 256), 256>>>(mags + i * specL, phases + i * specL, ft);

        gemm_mma<128, 512, 1><<<dim3(256, 4, NB), 512, SMEM>>>(
            w1h + (size_t)i * HID * DIM, w1l + (size_t)i * HID * DIM,
            hh, hl, b1 + i * HID, nullptr, yh, yl);
        gemm_mma<512, 128, 0><<<dim3(256, 1, NB), 512, SMEM>>>(
            w2h + (size_t)i * DIM * HID, w2l + (size_t)i * DIM * HID,
            yh, yl, b2 + i * DIM, z, nullptr, nullptr);

        fft_row_fwd<<<dim3(NB * DIM, 16), 256>>>(z, xf);
        fft_col<<<(NB * DIM * WHF) / 16, 256>>>(xf, ft);
        fft_row_inv<<<dim3(NB * DIM, 16), 256>>>(xf, zh, zl);

        gemm_mma<128, 128, 2><<<dim3(256, 1, NB), 512, SMEM>>>(
            oxh + (size_t)i * DIM * DIM, oxl + (size_t)i * DIM * DIM,
            zh, zl, oxb + i * DIM, h, hh, hl);
    }

    dec_kernel<<<(NB * HW + 255) / 256, 256>>>(h, dw, db, out);
}

// round 9
// speedup vs baseline: 1.4667x; 1.0754x over previous
#include <cuda_runtime.h>
#include <cuda_bf16.h>
#include <math.h>
#include <stdint.h>

#define HH   256
#define HW   65536
#define WHF  129
#define DIM  128
#define HID  512
#define NB   4
#define NLAYERS 4

typedef __nv_bfloat16 bf16;

// ---------------- scratch (device globals) ----------------
__device__ float  g_h[(size_t)NB * DIM * HW];          // residual [b][c][p]
__device__ float  g_z[(size_t)NB * DIM * HW];          // fft input
__device__ float2 g_xf[(size_t)NB * DIM * WHF * 256];
__device__ float2 g_filt[(size_t)DIM * WHF * 256];
__device__ bf16   g_h16h[(size_t)NB * DIM * HW];
__device__ bf16   g_h16l[(size_t)NB * DIM * HW];
__device__ bf16   g_y16h[(size_t)NB * HID * HW];
__device__ bf16   g_y16l[(size_t)NB * HID * HW];
__device__ bf16   g_z16h[(size_t)NB * DIM * HW];
__device__ bf16   g_z16l[(size_t)NB * DIM * HW];
__device__ bf16   g_w1h[(size_t)NLAYERS * HID * DIM], g_w1l[(size_t)NLAYERS * HID * DIM];
__device__ bf16   g_w2h[(size_t)NLAYERS * DIM * HID], g_w2l[(size_t)NLAYERS * DIM * HID];
__device__ bf16   g_oxh[(size_t)NLAYERS * DIM * DIM], g_oxl[(size_t)NLAYERS * DIM * DIM];

// ---------------- helpers ----------------
// base-4 digit reversal of an 8-bit index (radix-4 FFT ordering)
__device__ __forceinline__ int drev4(int x) {
    return ((x & 3) << 6) | (((x >> 2) & 3) << 4) | (((x >> 4) & 3) << 2) | ((x >> 6) & 3);
}
__device__ __forceinline__ float2 cadd(float2 a, float2 b){ return make_float2(a.x+b.x, a.y+b.y); }
__device__ __forceinline__ float2 csub(float2 a, float2 b){ return make_float2(a.x-b.x, a.y-b.y); }
__device__ __forceinline__ float2 cmul(float2 a, float2 b){
    return make_float2(a.x*b.x - a.y*b.y, a.x*b.y + a.y*b.x);
}
__device__ __forceinline__ uint32_t smem_u32(const void* p) {
    uint32_t a;
    asm("{ .reg .u64 t; cvta.to.shared.u64 t, %1; cvt.u32.u64 %0, t; }" : "=r"(a) : "l"(p));
    return a;
}
__device__ __forceinline__ uint32_t pack_hi(float a, float b) {
    return ((uint32_t)__bfloat16_as_ushort(__float2bfloat16(b)) << 16)
         |  (uint32_t)__bfloat16_as_ushort(__float2bfloat16(a));
}
__device__ __forceinline__ uint32_t pack_lo(float a, float b) {
    float ra = a - __bfloat162float(__float2bfloat16(a));
    float rb = b - __bfloat162float(__float2bfloat16(b));
    return ((uint32_t)__bfloat16_as_ushort(__float2bfloat16(rb)) << 16)
         |  (uint32_t)__bfloat16_as_ushort(__float2bfloat16(ra));
}

// ================= mma.sync primitives =================
__device__ __forceinline__ void ldsm4(uint32_t* r, uint32_t addr) {
    asm volatile("ldmatrix.sync.aligned.m8n8.x4.shared.b16 {%0,%1,%2,%3}, [%4];"
                 : "=r"(r[0]), "=r"(r[1]), "=r"(r[2]), "=r"(r[3]) : "r"(addr));
}
__device__ __forceinline__ void ldsm4t(uint32_t* r, uint32_t addr) {
    asm volatile("ldmatrix.sync.aligned.m8n8.x4.trans.shared.b16 {%0,%1,%2,%3}, [%4];"
                 : "=r"(r[0]), "=r"(r[1]), "=r"(r[2]), "=r"(r[3]) : "r"(addr));
}
__device__ __forceinline__ void mma16816(float* c, const uint32_t* a, const uint32_t* b) {
    asm volatile(
        "mma.sync.aligned.m16n8k16.row.col.f32.bf16.bf16.f32 "
        "{%0,%1,%2,%3}, {%4,%5,%6,%7}, {%8,%9}, {%0,%1,%2,%3};"
        : "+f"(c[0]), "+f"(c[1]), "+f"(c[2]), "+f"(c[3])
        : "r"(a[0]), "r"(a[1]), "r"(a[2]), "r"(a[3]), "r"(b[0]), "r"(b[1]));
}
__device__ __forceinline__ void cp16(uint32_t dst, const void* src) {
    asm volatile("cp.async.cg.shared.global [%0], [%1], 16;" :: "r"(dst), "l"(src));
}

// ================= wide pipelined bf16 tensor-core GEMM (R8, verified) =================
template <int K, int M, int EPI>
__global__ void __launch_bounds__(512, 1)
gemm_mma(const bf16* __restrict__ Ah, const bf16* __restrict__ Al,
         const bf16* __restrict__ Bh, const bf16* __restrict__ Bl,
         const float* __restrict__ bias,
         float* __restrict__ Cf, bf16* __restrict__ Ch, bf16* __restrict__ Cl)
{
    constexpr int NC = K / 32;
    constexpr int STAGE = 49152;
    extern __shared__ uint8_t smem[];
    uint32_t sbase = smem_u32(smem);

    int tid  = threadIdx.x;
    int lane = tid & 31;
    int warp = tid >> 5;
    int wm = warp >> 2, wn = warp & 3;

    const bf16* Ahp = Ah + (size_t)blockIdx.y * 128 * K;
    const bf16* Alp = Al + (size_t)blockIdx.y * 128 * K;
    const bf16* Bhp = Bh + (size_t)blockIdx.z * K * HW + blockIdx.x * 256;
    const bf16* Blp = Bl + (size_t)blockIdx.z * K * HW + blockIdx.x * 256;

    const bf16* gp[6];
    uint32_t    off[6];
    {
        int tile = tid >> 5, line = tid & 31;
        int am  = ((tile >> 1) << 4) + (line & 15);
        int agg = ((tile & 1) << 1) + (line >> 4);
        size_t aoff = (size_t)am * K + agg * 8;
        gp[0] = Ahp + aoff;  gp[1] = Alp + aoff;
        off[0] = tile * 512 + line * 16;
        off[1] = off[0] + 8192;
        int bk  = line & 15;
        int bgn = (tile & 15) * 2 + (line >> 4);
        size_t b0 = (size_t)bk * HW + bgn * 8;
        size_t b1 = (size_t)(bk + 16) * HW + bgn * 8;
        gp[2] = Bhp + b0;  gp[3] = Bhp + b1;
        gp[4] = Blp + b0;  gp[5] = Blp + b1;
        off[2] = 16384 + tile * 512 + line * 16;
        off[3] = 16384 + (tile + 16) * 512 + line * 16;
        off[4] = off[2] + 16384;
        off[5] = off[3] + 16384;
    }

    auto issue = [&](int c) {
        uint32_t sst = sbase + (c % 3) * STAGE;
        cp16(sst + off[0], gp[0]);  gp[0] += 32;
        cp16(sst + off[1], gp[1]);  gp[1] += 32;
        cp16(sst + off[2], gp[2]);  gp[2] += (size_t)32 * HW;
        cp16(sst + off[3], gp[3]);  gp[3] += (size_t)32 * HW;
        cp16(sst + off[4], gp[4]);  gp[4] += (size_t)32 * HW;
        cp16(sst + off[5], gp[5]);  gp[5] += (size_t)32 * HW;
        asm volatile("cp.async.commit_group;" ::: "memory");
    };

    float acc[2][8][4] = {};

    issue(0);
    if (NC > 1) issue(1);

    for (int c = 0; c < NC; c++) {
        if (c + 1 < NC) {
            asm volatile("cp.async.wait_group 1;" ::: "memory");
        } else {
            asm volatile("cp.async.wait_group 0;" ::: "memory");
        }
        __syncthreads();
        uint32_t st = sbase + (c % 3) * STAGE;
#pragma unroll
        for (int kb = 0; kb < 2; kb++) {
            uint32_t ah[2][4], al[2][4];
#pragma unroll
            for (int i = 0; i < 2; i++) {
                uint32_t ad = st + ((((wm * 2 + i) * 2) + kb) << 9) + lane * 16;
                ldsm4(ah[i], ad);
                ldsm4(al[i], ad + 8192);
            }
#pragma unroll
            for (int r = 0; r < 4; r++) {
                uint32_t bh[4], bl[4];
                uint32_t bd = st + 16384 + ((kb * 16 + wn * 4 + r) << 9) + lane * 16;
                ldsm4t(bh, bd);
                ldsm4t(bl, bd + 16384);
#pragma unroll
                for (int i = 0; i < 2; i++)
#pragma unroll
                    for (int hh = 0; hh < 2; hh++) {
                        float* a_ = acc[i][r * 2 + hh];
                        mma16816(a_, ah[i], &bh[hh * 2]);
                        mma16816(a_, ah[i], &bl[hh * 2]);
                        mma16816(a_, al[i], &bh[hh * 2]);
                    }
            }
        }
        __syncthreads();
        if (c + 2 < NC) issue(c + 2);
    }

    int g = lane >> 2;
    int mb0   = blockIdx.y * 128 + wm * 32;
    int nbase = blockIdx.x * 256 + wn * 64 + (lane & 3) * 2;
    size_t batch = (size_t)blockIdx.z * M * HW;
#pragma unroll
    for (int i = 0; i < 2; i++) {
        int r0 = mb0 + i * 16 + g;
        float bi0 = bias[r0], bi1 = bias[r0 + 8];
        size_t o0 = batch + (size_t)r0 * HW + nbase;
        size_t o1 = o0 + (size_t)8 * HW;
#pragma unroll
        for (int j = 0; j < 8; j++) {
            float v0 = acc[i][j][0] + bi0, v1 = acc[i][j][1] + bi0;
            float v2 = acc[i][j][2] + bi1, v3 = acc[i][j][3] + bi1;
            if (EPI == 1) {
                v0 = v0 / (1.f + __expf(-v0)); v1 = v1 / (1.f + __expf(-v1));
                v2 = v2 / (1.f + __expf(-v2)); v3 = v3 / (1.f + __expf(-v3));
            }
            if (EPI == 2) {
                float2 r0f = *(float2*)(Cf + o0 + j * 8);
                float2 r1f = *(float2*)(Cf + o1 + j * 8);
                v0 += r0f.x; v1 += r0f.y; v2 += r1f.x; v3 += r1f.y;
            }
            if (EPI == 0 || EPI == 2) {
                *(float2*)(Cf + o0 + j * 8) = make_float2(v0, v1);
                *(float2*)(Cf + o1 + j * 8) = make_float2(v2, v3);
            }
            if (EPI == 1 || EPI == 2) {
                *(uint32_t*)(Ch + o0 + j * 8) = pack_hi(v0, v1);
                *(uint32_t*)(Cl + o0 + j * 8) = pack_lo(v0, v1);
                *(uint32_t*)(Ch + o1 + j * 8) = pack_hi(v2, v3);
                *(uint32_t*)(Cl + o1 + j * 8) = pack_lo(v2, v3);
            }
        }
    }
}

// ---------------- weight split ----------------
__global__ void wsplit(const float* __restrict__ w, bf16* __restrict__ wh,
                       bf16* __restrict__ wl, int n)
{
    int i = blockIdx.x * 256 + threadIdx.x;
    if (i >= n) return;
    float v = w[i];
    bf16 h = __float2bfloat16(v);
    wh[i] = h;
    wl[i] = __float2bfloat16(v - __bfloat162float(h));
}

// ---------------- radix-4 FFT building blocks ----------------
// tw[k] = exp(-2*pi*i*k/256), k in [0,256)
#define TW_INIT256()                                                     \
    do { { float s_, c_;                                                 \
        sincospif(-(float)threadIdx.x / 128.0f, &s_, &c_);               \
        tw[threadIdx.x] = make_float2(c_, s_); } } while (0)

// DIF radix-4: natural input -> base-4 digit-reversed output. 4 stages.
#define FFT4_DIF(dmat)                                                   \
    for (int s_ = 0; s_ < 4; s_++) {                                     \
        __syncthreads();                                                 \
        int q_  = 64 >> (2 * s_);                                        \
        int ts_ = 1 << (2 * s_);                                         \
        for (int u_ = threadIdx.x; u_ < 1024; u_ += 256) {               \
            int r_ = u_ >> 6, w_ = u_ & 63;                              \
            int j_ = w_ & (q_ - 1);                                      \
            int b_ = (w_ >> (6 - 2 * s_)) << (8 - 2 * s_);               \
            float2 a_  = dmat[r_][b_ + j_];                              \
            float2 bb_ = dmat[r_][b_ + j_ + q_];                         \
            float2 c_  = dmat[r_][b_ + j_ + 2 * q_];                     \
            float2 dd_ = dmat[r_][b_ + j_ + 3 * q_];                     \
            float2 t0 = cadd(a_, c_),  t1 = csub(a_, c_);                \
            float2 t2 = cadd(bb_, dd_), t3 = csub(bb_, dd_);             \
            float2 t3i = make_float2(t3.y, -t3.x);                       \
            int e_ = j_ * ts_;                                           \
            dmat[r_][b_ + j_]          = cadd(t0, t2);                   \
            dmat[r_][b_ + j_ + q_]     = cmul(cadd(t1, t3i), tw[e_]);    \
            dmat[r_][b_ + j_ + 2*q_]   = cmul(csub(t0, t2), tw[2*e_]);   \
            dmat[r_][b_ + j_ + 3*q_]   = cmul(csub(t1, t3i), tw[3*e_]);  \
        }                                                                \
    }                                                                    \
    __syncthreads();

// DIT radix-4 inverse (conj twiddles, unscaled): digit-reversed input -> natural.
#define FFT4_DIT_INV(dmat)                                               \
    for (int s_ = 0; s_ < 4; s_++) {                                     \
        __syncthreads();                                                 \
        int q_  = 1 << (2 * s_);                                         \
        int ts_ = 64 >> (2 * s_);                                        \
        for (int u_ = threadIdx.x; u_ < 1024; u_ += 256) {               \
            int r_ = u_ >> 6, w_ = u_ & 63;                              \
            int j_ = w_ & (q_ - 1);                                      \
            int b_ = (w_ >> (2 * s_)) << (2 * s_ + 2);                   \
            int e_ = j_ * ts_;                                           \
            float2 w1 = tw[e_];     w1.y = -w1.y;                        \
            float2 w2 = tw[2*e_];   w2.y = -w2.y;                        \
            float2 w3 = tw[3*e_];   w3.y = -w3.y;                        \
            float2 a_  = dmat[r_][b_ + j_];                              \
            float2 bb_ = cmul(dmat[r_][b_ + j_ + q_], w1);               \
            float2 c_  = cmul(dmat[r_][b_ + j_ + 2 * q_], w2);           \
            float2 dd_ = cmul(dmat[r_][b_ + j_ + 3 * q_], w3);           \
            float2 t0 = cadd(a_, c_),  t1 = csub(a_, c_);                \
            float2 t2 = cadd(bb_, dd_), t3 = csub(bb_, dd_);             \
            float2 t3i = make_float2(-t3.y, t3.x);                       \
            dmat[r_][b_ + j_]        = cadd(t0, t2);                     \
            dmat[r_][b_ + j_ + q_]   = cadd(t1, t3i);                    \
            dmat[r_][b_ + j_ + 2*q_] = csub(t0, t2);                     \
            dmat[r_][b_ + j_ + 3*q_] = csub(t1, t3i);                    \
        }                                                                \
    }                                                                    \
    __syncthreads();

__global__ void fft_row_fwd(const float* __restrict__ z, float2* __restrict__ xf)
{
    __shared__ float2 d[16][256];
    __shared__ float2 tw[256];
    TW_INIT256();
    int img = blockIdx.x;
    int y0  = blockIdx.y * 16;
    const float* src = z + (size_t)img * HW + (size_t)y0 * 256;
    for (int idx = threadIdx.x; idx < 4096; idx += 256)
        d[idx >> 8][idx & 255] = make_float2(src[idx], 0.f);
    FFT4_DIF(d);
    float2* dst = xf + (size_t)img * (WHF * 256) + y0;
    for (int idx = threadIdx.x; idx < WHF * 16; idx += 256) {
        int kx = idx >> 4, ry = idx & 15;
        dst[(size_t)kx * 256 + ry] = d[ry][drev4(kx)];
    }
}

__global__ void fft_col(float2* __restrict__ xf, const float2* __restrict__ filt)
{
    __shared__ float2 d[16][256];
    __shared__ float2 tw[256];
    TW_INIT256();
    size_t l0 = (size_t)blockIdx.x * 16;
    float2* src = xf + l0 * 256;
    float2* df = &d[0][0];
    for (int idx = threadIdx.x; idx < 4096; idx += 256)
        df[idx] = src[idx];
    FFT4_DIF(d);
    for (int idx = threadIdx.x; idx < 4096; idx += 256) {
        int r = idx >> 8;
        size_t fl = ((l0 + r) % (size_t)(DIM * WHF)) * 256;
        float2 f = filt[fl + (idx & 255)];
        df[idx] = cmul(df[idx], f);
    }
    FFT4_DIT_INV(d);
    for (int idx = threadIdx.x; idx < 4096; idx += 256)
        src[idx] = df[idx];
}

__global__ void fft_row_inv(const float2* __restrict__ xf,
                            bf16* __restrict__ zh, bf16* __restrict__ zl)
{
    __shared__ float2 d[16][256];
    __shared__ float2 tw[256];
    TW_INIT256();
    int img = blockIdx.x;
    int y0  = blockIdx.y * 16;
    const float2* src = xf + (size_t)img * (WHF * 256) + y0;
    for (int idx = threadIdx.x; idx < WHF * 16; idx += 256) {
        int kx = idx >> 4, ry = idx & 15;
        d[ry][drev4(kx)] = src[(size_t)kx * 256 + ry];
    }
    __syncthreads();
    // Hermitian fill: X[k] = conj(X[256-k]) for k=129..255 (digit-reversed slots)
    for (int q = threadIdx.x; q < 16 * 127; q += 256) {
        int r = q / 127;
        int k = 129 + (q % 127);
        float2 v = d[r][drev4(256 - k)];
        d[r][drev4(k)] = make_float2(v.x, -v.y);
    }
    FFT4_DIT_INV(d);
    size_t o = (size_t)img * HW + (size_t)y0 * 256;
    for (int idx = threadIdx.x; idx < 2048; idx += 256) {
        float v0 = d[idx >> 7][(idx & 127) * 2].x;
        float v1 = d[idx >> 7][(idx & 127) * 2 + 1].x;
        *(uint32_t*)(zh + o + idx * 2) = pack_hi(v0, v1);
        *(uint32_t*)(zl + o + idx * 2) = pack_lo(v0, v1);
    }
}

// ---------------- enc / dec / filter ----------------
__global__ void enc_kernel(const float* __restrict__ x, const float* __restrict__ w,
                           const float* __restrict__ bias, const float* __restrict__ pos,
                           float* __restrict__ h, bf16* __restrict__ hh, bf16* __restrict__ hl)
{
    int idx = blockIdx.x * 256 + threadIdx.x;
    if (idx >= NB * DIM * HW / 2) return;
    int e = idx * 2;
    int p = e & (HW - 1);
    int o = (e >> 16) & (DIM - 1);
    int b = e >> 23;
    float x0 = x[(size_t)(b * 2 + 0) * HW + p];
    float x1 = x[(size_t)(b * 2 + 1) * HW + p];
    float x0b = x[(size_t)(b * 2 + 0) * HW + p + 1];
    float x1b = x[(size_t)(b * 2 + 1) * HW + p + 1];
    float w0 = w[o * 2], w1 = w[o * 2 + 1], bb = bias[o];
    float v0 = (w0 * x0 + w1 * x1 + bb) * 8.0f + pos[(size_t)o * HW + p];
    float v1 = (w0 * x0b + w1 * x1b + bb) * 8.0f + pos[(size_t)o * HW + p + 1];
    *(float2*)(h + e) = make_float2(v0, v1);
    *(uint32_t*)(hh + e) = pack_hi(v0, v1);
    *(uint32_t*)(hl + e) = pack_lo(v0, v1);
}

__global__ void dec_kernel(const float* __restrict__ h, const float* __restrict__ w,
                           const float* __restrict__ bias, float* __restrict__ out)
{
    int idx = blockIdx.x * 256 + threadIdx.x;
    if (idx >= NB * HW) return;
    int p = idx & (HW - 1);
    int b = idx >> 16;
    const float* hb = h + (size_t)b * DIM * HW + p;
    float a0 = 0.f, a1 = 0.f;
#pragma unroll 4
    for (int c = 0; c < DIM; c++) {
        float hv = hb[(size_t)c * HW];
        a0 += w[c] * hv;
        a1 += w[DIM + c] * hv;
    }
    out[(size_t)(b * 2 + 0) * HW + p] = (a0 + bias[0]) * 0.125f;
    out[(size_t)(b * 2 + 1) * HW + p] = (a1 + bias[1]) * 0.125f;
}

__global__ void prep_filt(const float* __restrict__ mags, const float* __restrict__ phases,
                          float2* __restrict__ filt)
{
    int idx = blockIdx.x * 256 + threadIdx.x;
    if (idx >= DIM * HH * WHF) return;
    int kx = idx % WHF;
    int ky = (idx / WHF) % HH;
    int c  = idx / (WHF * HH);
    int kyp = (ky <= 128) ? ky : (256 - ky);
    float2 o = make_float2(0.f, 0.f);
    if (kx * kx + kyp * kyp <= 16384) {
        float sig = 1.0f / (1.0f + __expf(-mags[idx]));
        float s, co;
        sincosf(phases[idx], &s, &co);
        float sc = sig * (1.0f / 65536.0f);
        o = make_float2(sc * co, sc * s);
    }
    filt[(size_t)c * (WHF * 256) + (size_t)kx * 256 + drev4(ky)] = o;
}

// ---------------- launch ----------------
extern "C" void kernel_launch(void* const* d_in, const int* in_sizes, int n_in,
                              void* d_out, int out_size)
{
    const float* x      = (const float*)d_in[0];
    const float* enc_w  = (const float*)d_in[1];
    const float* enc_b  = (const float*)d_in[2];
    const float* pos    = (const float*)d_in[3];
    const float* w1     = (const float*)d_in[4];
    const float* b1     = (const float*)d_in[5];
    const float* w2     = (const float*)d_in[6];
    const float* b2     = (const float*)d_in[7];
    const float* mags   = (const float*)d_in[8];
    const float* phases = (const float*)d_in[9];
    const float* oxw    = (const float*)d_in[10];
    const float* oxb    = (const float*)d_in[11];
    const float* dw     = (const float*)d_in[12];
    const float* db     = (const float*)d_in[13];
    float* out = (float*)d_out;

    float *h, *z;
    float2 *xf, *ft;
    bf16 *hh, *hl, *yh, *yl, *zh, *zl, *w1h, *w1l, *w2h, *w2l, *oxh, *oxl;
    cudaGetSymbolAddress((void**)&h,   g_h);
    cudaGetSymbolAddress((void**)&z,   g_z);
    cudaGetSymbolAddress((void**)&xf,  g_xf);
    cudaGetSymbolAddress((void**)&ft,  g_filt);
    cudaGetSymbolAddress((void**)&hh,  g_h16h);
    cudaGetSymbolAddress((void**)&hl,  g_h16l);
    cudaGetSymbolAddress((void**)&yh,  g_y16h);
    cudaGetSymbolAddress((void**)&yl,  g_y16l);
    cudaGetSymbolAddress((void**)&zh,  g_z16h);
    cudaGetSymbolAddress((void**)&zl,  g_z16l);
    cudaGetSymbolAddress((void**)&w1h, g_w1h);
    cudaGetSymbolAddress((void**)&w1l, g_w1l);
    cudaGetSymbolAddress((void**)&w2h, g_w2h);
    cudaGetSymbolAddress((void**)&w2l, g_w2l);
    cudaGetSymbolAddress((void**)&oxh, g_oxh);
    cudaGetSymbolAddress((void**)&oxl, g_oxl);

    const int SMEM = 3 * 49152;                      // 144 KB
    static bool attr = false;
    if (!attr) {
        cudaFuncSetAttribute(gemm_mma<128, 512, 1>, cudaFuncAttributeMaxDynamicSharedMemorySize, SMEM);
        cudaFuncSetAttribute(gemm_mma<512, 128, 0>, cudaFuncAttributeMaxDynamicSharedMemorySize, SMEM);
        cudaFuncSetAttribute(gemm_mma<128, 128, 2>, cudaFuncAttributeMaxDynamicSharedMemorySize, SMEM);
        attr = true;
    }

    wsplit<<<(NLAYERS * HID * DIM + 255) / 256, 256>>>(w1, w1h, w1l, NLAYERS * HID * DIM);
    wsplit<<<(NLAYERS * DIM * HID + 255) / 256, 256>>>(w2, w2h, w2l, NLAYERS * DIM * HID);
    wsplit<<<(NLAYERS * DIM * DIM + 255) / 256, 256>>>(oxw, oxh, oxl, NLAYERS * DIM * DIM);

    enc_kernel<<<(NB * DIM * HW / 2 + 255) / 256, 256>>>(x, enc_w, enc_b, pos, h, hh, hl);

    const size_t specL = (size_t)DIM * HH * WHF;
    for (int i = 0; i < NLAYERS; i++) {
        prep_filt<<<(int)((specL + 255) / 256), 256>>>(mags + i * specL, phases + i * specL, ft);

        gemm_mma<128, 512, 1><<<dim3(256, 4, NB), 512, SMEM>>>(
            w1h + (size_t)i * HID * DIM, w1l + (size_t)i * HID * DIM,
            hh, hl, b1 + i * HID, nullptr, yh, yl);
        gemm_mma<512, 128, 0><<<dim3(256, 1, NB), 512, SMEM>>>(
            w2h + (size_t)i * DIM * HID, w2l + (size_t)i * DIM * HID,
            yh, yl, b2 + i * DIM, z, nullptr, nullptr);

        fft_row_fwd<<<dim3(NB * DIM, 16), 256>>>(z, xf);
        fft_col<<<(NB * DIM * WHF) / 16, 256>>>(xf, ft);
        fft_row_inv<<<dim3(NB * DIM, 16), 256>>>(xf, zh, zl);

        gemm_mma<128, 128, 2><<<dim3(256, 1, NB), 512, SMEM>>>(
            oxh + (size_t)i * DIM * DIM, oxl + (size_t)i * DIM * DIM,
            zh, zl, oxb + i * DIM, h, hh, hl);
    }

    dec_kernel<<<(NB * HW + 255) / 256, 256>>>(h, dw, db, out);
}